// round 1
// baseline (speedup 1.0000x reference)
#include <cuda_runtime.h>

#define Bn 1024
#define Tn 256
#define Cn 384
#define Hn 64

// Scratch for projected Q, K, V (each 64 MiB). Device globals: allowed.
__device__ float g_q[Bn * Tn * Hn];
__device__ float g_k[Bn * Tn * Hn];
__device__ float g_v[Bn * Tn * Hn];

// ---------------------------------------------------------------------------
// Fused QKV projection: out[r,h] = sum_c x[r,c] * W[c,h] for W in {Wq,Wk,Wv}.
// Grid: (B*T)/64 blocks, 256 threads. Each thread: 8 rows x 2 cols x 3 mats.
// ---------------------------------------------------------------------------
__global__ __launch_bounds__(256) void proj_kernel(
    const float* __restrict__ x,
    const float* __restrict__ Wk,
    const float* __restrict__ Wq,
    const float* __restrict__ Wv)
{
    __shared__ float sX[64][32];    // rows x kc
    __shared__ float sWq[32][64];   // kc x cols
    __shared__ float sWk[32][64];
    __shared__ float sWv[32][64];

    const int tid = threadIdx.x;
    const int c0  = tid & 31;      // col (and col+32)
    const int rg  = tid >> 5;      // row group 0..7 -> rows rg*8 .. rg*8+7
    const int row0 = blockIdx.x * 64;

    float aq[8][2], ak[8][2], av[8][2];
#pragma unroll
    for (int i = 0; i < 8; ++i) {
        aq[i][0] = aq[i][1] = 0.f;
        ak[i][0] = ak[i][1] = 0.f;
        av[i][0] = av[i][1] = 0.f;
    }

    for (int kc = 0; kc < Cn; kc += 32) {
        __syncthreads();
        // load x tile 64x32 (coalesced)
#pragma unroll
        for (int j = 0; j < 8; ++j) {
            int idx = tid + j * 256;
            int r = idx >> 5, cc = idx & 31;
            sX[r][cc] = x[(row0 + r) * Cn + kc + cc];
        }
        // load W tiles 32x64 each (coalesced; W chunk at kc*64 + idx)
#pragma unroll
        for (int j = 0; j < 8; ++j) {
            int idx = tid + j * 256;
            ((float*)sWq)[idx] = Wq[kc * Hn + idx];
            ((float*)sWk)[idx] = Wk[kc * Hn + idx];
            ((float*)sWv)[idx] = Wv[kc * Hn + idx];
        }
        __syncthreads();

#pragma unroll 8
        for (int kk = 0; kk < 32; ++kk) {
            float wq0 = sWq[kk][c0], wq1 = sWq[kk][c0 + 32];
            float wk0 = sWk[kk][c0], wk1 = sWk[kk][c0 + 32];
            float wv0 = sWv[kk][c0], wv1 = sWv[kk][c0 + 32];
#pragma unroll
            for (int i = 0; i < 8; ++i) {
                float xv = sX[rg * 8 + i][kk];   // warp-uniform broadcast
                aq[i][0] += xv * wq0; aq[i][1] += xv * wq1;
                ak[i][0] += xv * wk0; ak[i][1] += xv * wk1;
                av[i][0] += xv * wv0; av[i][1] += xv * wv1;
            }
        }
    }

#pragma unroll
    for (int i = 0; i < 8; ++i) {
        int r = row0 + rg * 8 + i;
        g_q[r * Hn + c0]      = aq[i][0];
        g_q[r * Hn + c0 + 32] = aq[i][1];
        g_k[r * Hn + c0]      = ak[i][0];
        g_k[r * Hn + c0 + 32] = ak[i][1];
        g_v[r * Hn + c0]      = av[i][0];
        g_v[r * Hn + c0 + 32] = av[i][1];
    }
}

// ---------------------------------------------------------------------------
// Flash-attention (causal, online softmax).
// Grid: (T/64, B), 256 threads. Block handles one (batch, 64-row q-tile).
// Warp w owns q rows w*8..w*8+7. For S: lane -> kcols (lane, lane+32).
// For PV/output: lane -> h cols (lane, lane+32).
// ---------------------------------------------------------------------------
#define SQ_OFF   0
#define SK_OFF   (64 * 64)
#define SV_OFF   (SK_OFF + 64 * 65)
#define SS_OFF   (SV_OFF + 64 * 65)
#define SM_OFF   (SS_OFF + 64 * 65)
#define SL_OFF   (SM_OFF + 64)
#define SF_OFF   (SL_OFF + 64)
#define SMEM_FLOATS (SF_OFF + 64)

__global__ __launch_bounds__(256) void attn_kernel(float* __restrict__ out)
{
    extern __shared__ float sm[];
    float* sQ   = sm + SQ_OFF;   // [64][64]
    float* sK   = sm + SK_OFF;   // [64][65] (pad kills kcol-stride conflicts)
    float* sV   = sm + SV_OFF;   // [64][65]
    float* sS   = sm + SS_OFF;   // [64][65]
    float* sM   = sm + SM_OFF;   // [64] running row max
    float* sL   = sm + SL_OFF;   // [64] running row sum
    float* sFac = sm + SF_OFF;   // [64] rescale factor this tile

    const int tid  = threadIdx.x;
    const int qt   = blockIdx.x;
    const int b    = blockIdx.y;
    const int lane = tid & 31;
    const int qg   = tid >> 5;          // warp id: q rows qg*8..+7
    const int qbase = (b * Tn + qt * 64) * Hn;

    // Load Q tile, pre-scaled by H^-0.5 = 0.125
#pragma unroll
    for (int j = 0; j < 16; ++j) {
        int idx = tid + j * 256;
        sQ[idx] = g_q[qbase + idx] * 0.125f;
    }
    if (tid < 64) { sM[tid] = -1e30f; sL[tid] = 0.f; }

    float acc[8][2];
#pragma unroll
    for (int i = 0; i < 8; ++i) { acc[i][0] = 0.f; acc[i][1] = 0.f; }

    for (int kt = 0; kt <= qt; ++kt) {
        __syncthreads();   // Q ready (iter 0) / previous PV reads done
        const int kbase = (b * Tn + kt * 64) * Hn;
#pragma unroll
        for (int j = 0; j < 16; ++j) {
            int idx = tid + j * 256;
            int r = idx >> 6, h = idx & 63;
            sK[r * 65 + h] = g_k[kbase + idx];
            sV[r * 65 + h] = g_v[kbase + idx];
        }
        __syncthreads();

        // --- S = Q K^T (scaled) ---
        float s0[8], s1[8];
#pragma unroll
        for (int i = 0; i < 8; ++i) { s0[i] = 0.f; s1[i] = 0.f; }
#pragma unroll 8
        for (int h = 0; h < 64; ++h) {
            float k0 = sK[lane * 65 + h];
            float k1 = sK[(lane + 32) * 65 + h];
#pragma unroll
            for (int i = 0; i < 8; ++i) {
                float qv = sQ[(qg * 8 + i) * 64 + h];  // broadcast
                s0[i] += qv * k0;
                s1[i] += qv * k1;
            }
        }

        // --- causal mask + store to sS ---
        const bool diag = (kt == qt);
#pragma unroll
        for (int i = 0; i < 8; ++i) {
            int r = qg * 8 + i;
            float v0 = s0[i], v1 = s1[i];
            if (diag) {
                if (lane > r)      v0 = -1e30f;
                if (lane + 32 > r) v1 = -1e30f;
            }
            sS[r * 65 + lane]      = v0;
            sS[r * 65 + lane + 32] = v1;
        }
        __syncthreads();

        // --- per-row online softmax (one thread per row) ---
        if (tid < 64) {
            int row = tid;
            float mo = sM[row];
            float mt = mo;
#pragma unroll 8
            for (int k = 0; k < 64; ++k)
                mt = fmaxf(mt, sS[row * 65 + k]);
            float fac = __expf(mo - mt);
            float sum = 0.f;
#pragma unroll 8
            for (int k = 0; k < 64; ++k) {
                float p = __expf(sS[row * 65 + k] - mt);
                sS[row * 65 + k] = p;
                sum += p;
            }
            sL[row]   = sL[row] * fac + sum;
            sM[row]   = mt;
            sFac[row] = fac;
        }
        __syncthreads();

        // --- O = O*fac + P V ---
#pragma unroll
        for (int i = 0; i < 8; ++i) {
            float f = sFac[qg * 8 + i];
            acc[i][0] *= f;
            acc[i][1] *= f;
        }
#pragma unroll 8
        for (int k = 0; k < 64; ++k) {
            float v0 = sV[k * 65 + lane];
            float v1 = sV[k * 65 + lane + 32];
#pragma unroll
            for (int i = 0; i < 8; ++i) {
                float p = sS[(qg * 8 + i) * 65 + k];  // broadcast
                acc[i][0] += p * v0;
                acc[i][1] += p * v1;
            }
        }
    }

    // --- normalize + write out ---
#pragma unroll
    for (int i = 0; i < 8; ++i) {
        int r = qg * 8 + i;
        float inv = 1.0f / sL[r];
        out[qbase + r * Hn + lane]      = acc[i][0] * inv;
        out[qbase + r * Hn + lane + 32] = acc[i][1] * inv;
    }
}

// ---------------------------------------------------------------------------
extern "C" void kernel_launch(void* const* d_in, const int* in_sizes, int n_in,
                              void* d_out, int out_size)
{
    const float* x  = (const float*)d_in[0];
    const float* Wk = (const float*)d_in[1];
    const float* Wq = (const float*)d_in[2];
    const float* Wv = (const float*)d_in[3];
    float* out = (float*)d_out;

    proj_kernel<<<(Bn * Tn) / 64, 256>>>(x, Wk, Wq, Wv);

    const int smem_bytes = SMEM_FLOATS * (int)sizeof(float);  // ~67 KB
    cudaFuncSetAttribute(attn_kernel,
                         cudaFuncAttributeMaxDynamicSharedMemorySize, smem_bytes);
    attn_kernel<<<dim3(Tn / 64, Bn), 256, smem_bytes>>>(out);
}

// round 2
// speedup vs baseline: 1.0001x; 1.0001x over previous
#include <cuda_runtime.h>

#define Bn 1024
#define Tn 256
#define Cn 384
#define Hn 64

// Scratch for projected Q, K, V (each 64 MiB). Device globals: allowed.
__device__ float g_q[Bn * Tn * Hn];
__device__ float g_k[Bn * Tn * Hn];
__device__ float g_v[Bn * Tn * Hn];

// ---------------------------------------------------------------------------
// Fused QKV projection: out[r,h] = sum_c x[r,c] * W[c,h] for W in {Wq,Wk,Wv}.
// Grid: (B*T)/64 blocks, 256 threads. Each thread: 8 rows x 2 cols x 3 mats.
// ---------------------------------------------------------------------------
__global__ __launch_bounds__(256) void proj_kernel(
    const float* __restrict__ x,
    const float* __restrict__ Wk,
    const float* __restrict__ Wq,
    const float* __restrict__ Wv)
{
    __shared__ float sX[64][32];    // rows x kc
    __shared__ float sWq[32][64];   // kc x cols
    __shared__ float sWk[32][64];
    __shared__ float sWv[32][64];

    const int tid = threadIdx.x;
    const int c0  = tid & 31;      // col (and col+32)
    const int rg  = tid >> 5;      // row group 0..7 -> rows rg*8 .. rg*8+7
    const int row0 = blockIdx.x * 64;

    float aq[8][2], ak[8][2], av[8][2];
#pragma unroll
    for (int i = 0; i < 8; ++i) {
        aq[i][0] = aq[i][1] = 0.f;
        ak[i][0] = ak[i][1] = 0.f;
        av[i][0] = av[i][1] = 0.f;
    }

    for (int kc = 0; kc < Cn; kc += 32) {
        __syncthreads();
        // load x tile 64x32 (coalesced)
#pragma unroll
        for (int j = 0; j < 8; ++j) {
            int idx = tid + j * 256;
            int r = idx >> 5, cc = idx & 31;
            sX[r][cc] = x[(row0 + r) * Cn + kc + cc];
        }
        // load W tiles 32x64 each (coalesced; W chunk at kc*64 + idx)
#pragma unroll
        for (int j = 0; j < 8; ++j) {
            int idx = tid + j * 256;
            ((float*)sWq)[idx] = Wq[kc * Hn + idx];
            ((float*)sWk)[idx] = Wk[kc * Hn + idx];
            ((float*)sWv)[idx] = Wv[kc * Hn + idx];
        }
        __syncthreads();

#pragma unroll 8
        for (int kk = 0; kk < 32; ++kk) {
            float wq0 = sWq[kk][c0], wq1 = sWq[kk][c0 + 32];
            float wk0 = sWk[kk][c0], wk1 = sWk[kk][c0 + 32];
            float wv0 = sWv[kk][c0], wv1 = sWv[kk][c0 + 32];
#pragma unroll
            for (int i = 0; i < 8; ++i) {
                float xv = sX[rg * 8 + i][kk];   // warp-uniform broadcast
                aq[i][0] += xv * wq0; aq[i][1] += xv * wq1;
                ak[i][0] += xv * wk0; ak[i][1] += xv * wk1;
                av[i][0] += xv * wv0; av[i][1] += xv * wv1;
            }
        }
    }

#pragma unroll
    for (int i = 0; i < 8; ++i) {
        int r = row0 + rg * 8 + i;
        g_q[r * Hn + c0]      = aq[i][0];
        g_q[r * Hn + c0 + 32] = aq[i][1];
        g_k[r * Hn + c0]      = ak[i][0];
        g_k[r * Hn + c0 + 32] = ak[i][1];
        g_v[r * Hn + c0]      = av[i][0];
        g_v[r * Hn + c0 + 32] = av[i][1];
    }
}

// ---------------------------------------------------------------------------
// Flash-attention (causal, online softmax).
// Grid: (T/64, B), 256 threads. Block handles one (batch, 64-row q-tile).
// Warp w owns q rows w*8..w*8+7. For S: lane -> kcols (lane, lane+32).
// For PV/output: lane -> h cols (lane, lane+32).
// ---------------------------------------------------------------------------
#define SQ_OFF   0
#define SK_OFF   (64 * 64)
#define SV_OFF   (SK_OFF + 64 * 65)
#define SS_OFF   (SV_OFF + 64 * 65)
#define SM_OFF   (SS_OFF + 64 * 65)
#define SL_OFF   (SM_OFF + 64)
#define SF_OFF   (SL_OFF + 64)
#define SMEM_FLOATS (SF_OFF + 64)

__global__ __launch_bounds__(256) void attn_kernel(float* __restrict__ out)
{
    extern __shared__ float sm[];
    float* sQ   = sm + SQ_OFF;   // [64][64]
    float* sK   = sm + SK_OFF;   // [64][65] (pad kills kcol-stride conflicts)
    float* sV   = sm + SV_OFF;   // [64][65]
    float* sS   = sm + SS_OFF;   // [64][65]
    float* sM   = sm + SM_OFF;   // [64] running row max
    float* sL   = sm + SL_OFF;   // [64] running row sum
    float* sFac = sm + SF_OFF;   // [64] rescale factor this tile

    const int tid  = threadIdx.x;
    const int qt   = blockIdx.x;
    const int b    = blockIdx.y;
    const int lane = tid & 31;
    const int qg   = tid >> 5;          // warp id: q rows qg*8..+7
    const int qbase = (b * Tn + qt * 64) * Hn;

    // Load Q tile, pre-scaled by H^-0.5 = 0.125
#pragma unroll
    for (int j = 0; j < 16; ++j) {
        int idx = tid + j * 256;
        sQ[idx] = g_q[qbase + idx] * 0.125f;
    }
    if (tid < 64) { sM[tid] = -1e30f; sL[tid] = 0.f; }

    float acc[8][2];
#pragma unroll
    for (int i = 0; i < 8; ++i) { acc[i][0] = 0.f; acc[i][1] = 0.f; }

    for (int kt = 0; kt <= qt; ++kt) {
        __syncthreads();   // Q ready (iter 0) / previous PV reads done
        const int kbase = (b * Tn + kt * 64) * Hn;
#pragma unroll
        for (int j = 0; j < 16; ++j) {
            int idx = tid + j * 256;
            int r = idx >> 6, h = idx & 63;
            sK[r * 65 + h] = g_k[kbase + idx];
            sV[r * 65 + h] = g_v[kbase + idx];
        }
        __syncthreads();

        // --- S = Q K^T (scaled) ---
        float s0[8], s1[8];
#pragma unroll
        for (int i = 0; i < 8; ++i) { s0[i] = 0.f; s1[i] = 0.f; }
#pragma unroll 8
        for (int h = 0; h < 64; ++h) {
            float k0 = sK[lane * 65 + h];
            float k1 = sK[(lane + 32) * 65 + h];
#pragma unroll
            for (int i = 0; i < 8; ++i) {
                float qv = sQ[(qg * 8 + i) * 64 + h];  // broadcast
                s0[i] += qv * k0;
                s1[i] += qv * k1;
            }
        }

        // --- causal mask + store to sS ---
        const bool diag = (kt == qt);
#pragma unroll
        for (int i = 0; i < 8; ++i) {
            int r = qg * 8 + i;
            float v0 = s0[i], v1 = s1[i];
            if (diag) {
                if (lane > r)      v0 = -1e30f;
                if (lane + 32 > r) v1 = -1e30f;
            }
            sS[r * 65 + lane]      = v0;
            sS[r * 65 + lane + 32] = v1;
        }
        __syncthreads();

        // --- per-row online softmax (one thread per row) ---
        if (tid < 64) {
            int row = tid;
            float mo = sM[row];
            float mt = mo;
#pragma unroll 8
            for (int k = 0; k < 64; ++k)
                mt = fmaxf(mt, sS[row * 65 + k]);
            float fac = __expf(mo - mt);
            float sum = 0.f;
#pragma unroll 8
            for (int k = 0; k < 64; ++k) {
                float p = __expf(sS[row * 65 + k] - mt);
                sS[row * 65 + k] = p;
                sum += p;
            }
            sL[row]   = sL[row] * fac + sum;
            sM[row]   = mt;
            sFac[row] = fac;
        }
        __syncthreads();

        // --- O = O*fac + P V ---
#pragma unroll
        for (int i = 0; i < 8; ++i) {
            float f = sFac[qg * 8 + i];
            acc[i][0] *= f;
            acc[i][1] *= f;
        }
#pragma unroll 8
        for (int k = 0; k < 64; ++k) {
            float v0 = sV[k * 65 + lane];
            float v1 = sV[k * 65 + lane + 32];
#pragma unroll
            for (int i = 0; i < 8; ++i) {
                float p = sS[(qg * 8 + i) * 65 + k];  // broadcast
                acc[i][0] += p * v0;
                acc[i][1] += p * v1;
            }
        }
    }

    // --- normalize + write out ---
#pragma unroll
    for (int i = 0; i < 8; ++i) {
        int r = qg * 8 + i;
        float inv = 1.0f / sL[r];
        out[qbase + r * Hn + lane]      = acc[i][0] * inv;
        out[qbase + r * Hn + lane + 32] = acc[i][1] * inv;
    }
}

// ---------------------------------------------------------------------------
extern "C" void kernel_launch(void* const* d_in, const int* in_sizes, int n_in,
                              void* d_out, int out_size)
{
    const float* x  = (const float*)d_in[0];
    const float* Wk = (const float*)d_in[1];
    const float* Wq = (const float*)d_in[2];
    const float* Wv = (const float*)d_in[3];
    float* out = (float*)d_out;

    proj_kernel<<<(Bn * Tn) / 64, 256>>>(x, Wk, Wq, Wv);

    const int smem_bytes = SMEM_FLOATS * (int)sizeof(float);  // ~67 KB
    cudaFuncSetAttribute(attn_kernel,
                         cudaFuncAttributeMaxDynamicSharedMemorySize, smem_bytes);
    attn_kernel<<<dim3(Tn / 64, Bn), 256, smem_bytes>>>(out);
}

// round 4
// speedup vs baseline: 1.4817x; 1.4815x over previous
#include <cuda_runtime.h>
#include <cuda_bf16.h>
#include <cstdint>

#define Bn 1024
#define Tn 256
#define Cn 384
#define Hn 64

// Scratch for projected Q, K, V. Device globals: allowed.
__device__ float g_q[Bn * Tn * Hn];
__device__ float g_k[Bn * Tn * Hn];
__device__ float g_v[Bn * Tn * Hn];

// Pre-packed B fragments for mma.sync.m16n8k16 (row.col):
// index ((kt*24 + nt)*32 + lane) -> {bhi_r0, bhi_r1, blo_r0, blo_r1}
// kt: 24 k-tiles of 16 over K=384; nt: 24 n-tiles of 8 over N=192 ([Q|K|V]).
__device__ uint4 g_bfrag[24 * 24 * 32];

// ---------------------------------------------------------------------------
__device__ __forceinline__ uint32_t smem_u32(const void* p) {
    uint32_t a;
    asm("{ .reg .u64 t; cvta.to.shared.u64 t, %1; cvt.u32.u64 %0, t; }" : "=r"(a) : "l"(p));
    return a;
}
__device__ __forceinline__ uint32_t pack_bf16(float a, float b) {
    uint32_t lo = __bfloat16_as_ushort(__float2bfloat16_rn(a));
    uint32_t hi = __bfloat16_as_ushort(__float2bfloat16_rn(b));
    return lo | (hi << 16);
}
__device__ __forceinline__ float bf16_hi_part(float v) {
    return __bfloat162float(__float2bfloat16_rn(v));
}
__device__ __forceinline__ void mma_bf16(float* c, const uint32_t* a,
                                         uint32_t b0, uint32_t b1) {
    asm volatile(
        "mma.sync.aligned.m16n8k16.row.col.f32.bf16.bf16.f32 "
        "{%0,%1,%2,%3}, {%4,%5,%6,%7}, {%8,%9}, {%0,%1,%2,%3};"
        : "+f"(c[0]), "+f"(c[1]), "+f"(c[2]), "+f"(c[3])
        : "r"(a[0]), "r"(a[1]), "r"(a[2]), "r"(a[3]), "r"(b0), "r"(b1));
}
__device__ __forceinline__ void ldmatrix_x4(uint32_t* r, uint32_t addr) {
    asm volatile(
        "ldmatrix.sync.aligned.m8n8.x4.shared.b16 {%0,%1,%2,%3}, [%4];"
        : "=r"(r[0]), "=r"(r[1]), "=r"(r[2]), "=r"(r[3]) : "r"(addr));
}

// ---------------------------------------------------------------------------
// Weight prep: build bf16 hi/lo B-fragments in the exact mma.sync register
// layout. 24kt x 24nt x 32 lanes = 18432 threads.
// ---------------------------------------------------------------------------
__global__ void prep_w_kernel(const float* __restrict__ Wk,
                              const float* __restrict__ Wq,
                              const float* __restrict__ Wv) {
    int idx = blockIdx.x * 256 + threadIdx.x;
    if (idx >= 24 * 24 * 32) return;
    int lane = idx & 31;
    int nt = (idx >> 5) % 24;
    int kt = (idx >> 5) / 24;

    int n = nt * 8 + (lane >> 2);            // global N col 0..191 ([Q|K|V])
    int k0 = kt * 16 + (lane & 3) * 2;       // k rows k0,k0+1 and k0+8,k0+9
    const float* W = (n < 64) ? Wq : (n < 128) ? Wk : Wv;
    int nc = n & 63;

    float w00 = W[(k0 + 0) * Hn + nc];
    float w01 = W[(k0 + 1) * Hn + nc];
    float w10 = W[(k0 + 8) * Hn + nc];
    float w11 = W[(k0 + 9) * Hn + nc];

    float h00 = bf16_hi_part(w00), h01 = bf16_hi_part(w01);
    float h10 = bf16_hi_part(w10), h11 = bf16_hi_part(w11);

    uint4 f;
    f.x = pack_bf16(w00, w01);               // hi reg0
    f.y = pack_bf16(w10, w11);               // hi reg1
    f.z = pack_bf16(w00 - h00, w01 - h01);   // lo reg0
    f.w = pack_bf16(w10 - h10, w11 - h11);   // lo reg1
    g_bfrag[idx] = f;
}

// ---------------------------------------------------------------------------
// Projection GEMM via mma.sync bf16 3-product split.
// Grid: 2048 blocks x 256 threads. Block tile M=128, N=192.
// Warp grid: 4 along M (warp M=32 -> 2 mtiles of 16), 2 along N (warp N=96
// -> 12 ntiles of 8). K streamed in 12 chunks of 32 (2 k-tiles), 2-stage smem.
// smem A rows have 80B stride -> conflict-free ldmatrix.
// ---------------------------------------------------------------------------
__global__ __launch_bounds__(256) void proj_mma_kernel(const float* __restrict__ x) {
    __shared__ uint32_t sA[2][2][128 * 20];   // [stage][hi/lo][row*20 + colu32]

    const int tid = threadIdx.x;
    const int wid = tid >> 5;
    const int lane = tid & 31;
    const int row0 = blockIdx.x * 128;

    const int wm = (wid & 3) * 32;            // warp M offset within block
    const int nw = wid >> 2;                  // 0/1 -> N half

    // x staging: thread owns row tid/2, 16 cols starting at (tid&1)*16
    const int xr = tid >> 1;
    const int xc = (tid & 1) * 16;
    const float* xrow = x + (size_t)(row0 + xr) * Cn + xc;

    float4 v[4];
#pragma unroll
    for (int j = 0; j < 4; ++j) v[j] = __ldg((const float4*)xrow + j);

    // store chunk 0 into stage 0
    {
        const int base = xr * 20 + xc / 2;
#pragma unroll
        for (int j = 0; j < 4; ++j) {
            float hx = bf16_hi_part(v[j].x), hy = bf16_hi_part(v[j].y);
            float hz = bf16_hi_part(v[j].z), hw = bf16_hi_part(v[j].w);
            sA[0][0][base + 2 * j + 0] = pack_bf16(v[j].x, v[j].y);
            sA[0][0][base + 2 * j + 1] = pack_bf16(v[j].z, v[j].w);
            sA[0][1][base + 2 * j + 0] = pack_bf16(v[j].x - hx, v[j].y - hy);
            sA[0][1][base + 2 * j + 1] = pack_bf16(v[j].z - hz, v[j].w - hw);
        }
    }
    __syncthreads();

    float acc[2][12][4];
#pragma unroll
    for (int mt = 0; mt < 2; ++mt)
#pragma unroll
        for (int nt = 0; nt < 12; ++nt)
#pragma unroll
            for (int e = 0; e < 4; ++e) acc[mt][nt][e] = 0.f;

    // ldmatrix lane addressing: row = lane&15, kcol8 = (lane>>4)*8
    const int lrow = lane & 15;
    const int lk8 = (lane >> 4) * 8;

    for (int c = 0; c < 12; ++c) {
        const int st = c & 1;

        if (c < 11) {
            const float* nx = xrow + (c + 1) * 32;
#pragma unroll
            for (int j = 0; j < 4; ++j) v[j] = __ldg((const float4*)nx + j);
        }

        const uint32_t aHiBase = smem_u32(&sA[st][0][0]);
        const uint32_t aLoBase = smem_u32(&sA[st][1][0]);

#pragma unroll
        for (int kt = 0; kt < 2; ++kt) {
            uint32_t ahi[2][4], alo[2][4];
#pragma unroll
            for (int mt = 0; mt < 2; ++mt) {
                uint32_t off = (uint32_t)((wm + mt * 16 + lrow) * 80 +
                                          (kt * 16 + lk8) * 2);
                ldmatrix_x4(ahi[mt], aHiBase + off);
                ldmatrix_x4(alo[mt], aLoBase + off);
            }
            const uint4* bp = g_bfrag + (size_t)(((c * 2 + kt) * 24 + nw * 12) * 32 + lane);
#pragma unroll
            for (int nt = 0; nt < 12; ++nt) {
                uint4 bf = __ldg(bp + nt * 32);
#pragma unroll
                for (int mt = 0; mt < 2; ++mt) {
                    mma_bf16(acc[mt][nt], ahi[mt], bf.x, bf.y);   // hi*hi
                    mma_bf16(acc[mt][nt], ahi[mt], bf.z, bf.w);   // hi*lo
                    mma_bf16(acc[mt][nt], alo[mt], bf.x, bf.y);   // lo*hi
                }
            }
        }

        if (c < 11) {
            __syncthreads();   // all warps done reading stage st^1 (chunk c-1)
            const int base = xr * 20 + xc / 2;
            const int so = st ^ 1;
#pragma unroll
            for (int j = 0; j < 4; ++j) {
                float hx = bf16_hi_part(v[j].x), hy = bf16_hi_part(v[j].y);
                float hz = bf16_hi_part(v[j].z), hw = bf16_hi_part(v[j].w);
                sA[so][0][base + 2 * j + 0] = pack_bf16(v[j].x, v[j].y);
                sA[so][0][base + 2 * j + 1] = pack_bf16(v[j].z, v[j].w);
                sA[so][1][base + 2 * j + 0] = pack_bf16(v[j].x - hx, v[j].y - hy);
                sA[so][1][base + 2 * j + 1] = pack_bf16(v[j].z - hz, v[j].w - hw);
            }
            __syncthreads();
        }
    }

    // Epilogue: C frag -> rows lane/4, lane/4+8; cols (lane&3)*2,+1
#pragma unroll
    for (int mt = 0; mt < 2; ++mt) {
#pragma unroll
        for (int nt = 0; nt < 12; ++nt) {
            int n = nw * 96 + nt * 8 + (lane & 3) * 2;
            float* dst = (n < 64) ? g_q : (n < 128) ? g_k : g_v;
            int ncol = n & 63;
            size_t r0g = (size_t)(row0 + wm + mt * 16 + (lane >> 2));
            *(float2*)&dst[r0g * Hn + ncol] =
                make_float2(acc[mt][nt][0], acc[mt][nt][1]);
            *(float2*)&dst[(r0g + 8) * Hn + ncol] =
                make_float2(acc[mt][nt][2], acc[mt][nt][3]);
        }
    }
}

// ---------------------------------------------------------------------------
// Flash-attention (causal, online softmax) — unchanged from R1 (passing).
// ---------------------------------------------------------------------------
#define SQ_OFF   0
#define SK_OFF   (64 * 64)
#define SV_OFF   (SK_OFF + 64 * 65)
#define SS_OFF   (SV_OFF + 64 * 65)
#define SM_OFF   (SS_OFF + 64 * 65)
#define SL_OFF   (SM_OFF + 64)
#define SF_OFF   (SL_OFF + 64)
#define SMEM_FLOATS (SF_OFF + 64)

__global__ __launch_bounds__(256) void attn_kernel(float* __restrict__ out)
{
    extern __shared__ float sm[];
    float* sQ   = sm + SQ_OFF;
    float* sK   = sm + SK_OFF;
    float* sV   = sm + SV_OFF;
    float* sS   = sm + SS_OFF;
    float* sM   = sm + SM_OFF;
    float* sL   = sm + SL_OFF;
    float* sFac = sm + SF_OFF;

    const int tid  = threadIdx.x;
    const int qt   = blockIdx.x;
    const int b    = blockIdx.y;
    const int lane = tid & 31;
    const int qg   = tid >> 5;
    const int qbase = (b * Tn + qt * 64) * Hn;

#pragma unroll
    for (int j = 0; j < 16; ++j) {
        int idx = tid + j * 256;
        sQ[idx] = g_q[qbase + idx] * 0.125f;
    }
    if (tid < 64) { sM[tid] = -1e30f; sL[tid] = 0.f; }

    float acc[8][2];
#pragma unroll
    for (int i = 0; i < 8; ++i) { acc[i][0] = 0.f; acc[i][1] = 0.f; }

    for (int kt = 0; kt <= qt; ++kt) {
        __syncthreads();
        const int kbase = (b * Tn + kt * 64) * Hn;
#pragma unroll
        for (int j = 0; j < 16; ++j) {
            int idx = tid + j * 256;
            int r = idx >> 6, h = idx & 63;
            sK[r * 65 + h] = g_k[kbase + idx];
            sV[r * 65 + h] = g_v[kbase + idx];
        }
        __syncthreads();

        float s0[8], s1[8];
#pragma unroll
        for (int i = 0; i < 8; ++i) { s0[i] = 0.f; s1[i] = 0.f; }
#pragma unroll 8
        for (int h = 0; h < 64; ++h) {
            float k0 = sK[lane * 65 + h];
            float k1 = sK[(lane + 32) * 65 + h];
#pragma unroll
            for (int i = 0; i < 8; ++i) {
                float qv = sQ[(qg * 8 + i) * 64 + h];
                s0[i] += qv * k0;
                s1[i] += qv * k1;
            }
        }

        const bool diag = (kt == qt);
#pragma unroll
        for (int i = 0; i < 8; ++i) {
            int r = qg * 8 + i;
            float v0 = s0[i], v1 = s1[i];
            if (diag) {
                if (lane > r)      v0 = -1e30f;
                if (lane + 32 > r) v1 = -1e30f;
            }
            sS[r * 65 + lane]      = v0;
            sS[r * 65 + lane + 32] = v1;
        }
        __syncthreads();

        if (tid < 64) {
            int row = tid;
            float mo = sM[row];
            float mt = mo;
#pragma unroll 8
            for (int k = 0; k < 64; ++k)
                mt = fmaxf(mt, sS[row * 65 + k]);
            float fac = __expf(mo - mt);
            float sum = 0.f;
#pragma unroll 8
            for (int k = 0; k < 64; ++k) {
                float p = __expf(sS[row * 65 + k] - mt);
                sS[row * 65 + k] = p;
                sum += p;
            }
            sL[row]   = sL[row] * fac + sum;
            sM[row]   = mt;
            sFac[row] = fac;
        }
        __syncthreads();

#pragma unroll
        for (int i = 0; i < 8; ++i) {
            float f = sFac[qg * 8 + i];
            acc[i][0] *= f;
            acc[i][1] *= f;
        }
#pragma unroll 8
        for (int k = 0; k < 64; ++k) {
            float v0 = sV[k * 65 + lane];
            float v1 = sV[k * 65 + lane + 32];
#pragma unroll
            for (int i = 0; i < 8; ++i) {
                float p = sS[(qg * 8 + i) * 65 + k];
                acc[i][0] += p * v0;
                acc[i][1] += p * v1;
            }
        }
    }

#pragma unroll
    for (int i = 0; i < 8; ++i) {
        int r = qg * 8 + i;
        float inv = 1.0f / sL[r];
        out[qbase + r * Hn + lane]      = acc[i][0] * inv;
        out[qbase + r * Hn + lane + 32] = acc[i][1] * inv;
    }
}

// ---------------------------------------------------------------------------
extern "C" void kernel_launch(void* const* d_in, const int* in_sizes, int n_in,
                              void* d_out, int out_size)
{
    const float* x  = (const float*)d_in[0];
    const float* Wk = (const float*)d_in[1];
    const float* Wq = (const float*)d_in[2];
    const float* Wv = (const float*)d_in[3];
    float* out = (float*)d_out;

    prep_w_kernel<<<(24 * 24 * 32 + 255) / 256, 256>>>(Wk, Wq, Wv);

    proj_mma_kernel<<<(Bn * Tn) / 128, 256>>>(x);

    const int smem_bytes = SMEM_FLOATS * (int)sizeof(float);
    cudaFuncSetAttribute(attn_kernel,
                         cudaFuncAttributeMaxDynamicSharedMemorySize, smem_bytes);
    attn_kernel<<<dim3(Tn / 64, Bn), 256, smem_bytes>>>(out);
}

// round 5
// speedup vs baseline: 1.4852x; 1.0024x over previous
#include <cuda_runtime.h>
#include <cuda_bf16.h>
#include <cstdint>

#define Bn 1024
#define Tn 256
#define Cn 384
#define Hn 64

// Scratch for projected Q, K, V. Device globals: allowed.
__device__ float g_q[Bn * Tn * Hn];
__device__ float g_k[Bn * Tn * Hn];
__device__ float g_v[Bn * Tn * Hn];

// Pre-packed B fragments for mma.sync.m16n8k16 (row.col):
// index ((kt*24 + nt)*32 + lane) -> {bhi_r0, bhi_r1, blo_r0, blo_r1}
// kt: 24 k-tiles of 16 over K=384; nt: 24 n-tiles of 8 over N=192 ([Q|K|V]).
__device__ uint4 g_bfrag[24 * 24 * 32];

// ---------------------------------------------------------------------------
__device__ __forceinline__ uint32_t smem_u32(const void* p) {
    uint32_t a;
    asm("{ .reg .u64 t; cvta.to.shared.u64 t, %1; cvt.u32.u64 %0, t; }" : "=r"(a) : "l"(p));
    return a;
}
__device__ __forceinline__ uint32_t pack_bf16(float a, float b) {
    uint32_t lo = __bfloat16_as_ushort(__float2bfloat16_rn(a));
    uint32_t hi = __bfloat16_as_ushort(__float2bfloat16_rn(b));
    return lo | (hi << 16);
}
__device__ __forceinline__ float bf16_hi_part(float v) {
    return __bfloat162float(__float2bfloat16_rn(v));
}
__device__ __forceinline__ void mma_bf16(float* c, const uint32_t* a,
                                         uint32_t b0, uint32_t b1) {
    asm volatile(
        "mma.sync.aligned.m16n8k16.row.col.f32.bf16.bf16.f32 "
        "{%0,%1,%2,%3}, {%4,%5,%6,%7}, {%8,%9}, {%0,%1,%2,%3};"
        : "+f"(c[0]), "+f"(c[1]), "+f"(c[2]), "+f"(c[3])
        : "r"(a[0]), "r"(a[1]), "r"(a[2]), "r"(a[3]), "r"(b0), "r"(b1));
}
__device__ __forceinline__ void ldmatrix_x4(uint32_t* r, uint32_t addr) {
    asm volatile(
        "ldmatrix.sync.aligned.m8n8.x4.shared.b16 {%0,%1,%2,%3}, [%4];"
        : "=r"(r[0]), "=r"(r[1]), "=r"(r[2]), "=r"(r[3]) : "r"(addr));
}

// ---------------------------------------------------------------------------
// Weight prep: build bf16 hi/lo B-fragments in the exact mma.sync register
// layout. 24kt x 24nt x 32 lanes = 18432 threads.
// ---------------------------------------------------------------------------
__global__ void prep_w_kernel(const float* __restrict__ Wk,
                              const float* __restrict__ Wq,
                              const float* __restrict__ Wv) {
    int idx = blockIdx.x * 256 + threadIdx.x;
    if (idx >= 24 * 24 * 32) return;
    int lane = idx & 31;
    int nt = (idx >> 5) % 24;
    int kt = (idx >> 5) / 24;

    int n = nt * 8 + (lane >> 2);            // global N col 0..191 ([Q|K|V])
    int k0 = kt * 16 + (lane & 3) * 2;       // k rows k0,k0+1 and k0+8,k0+9
    const float* W = (n < 64) ? Wq : (n < 128) ? Wk : Wv;
    int nc = n & 63;

    float w00 = W[(k0 + 0) * Hn + nc];
    float w01 = W[(k0 + 1) * Hn + nc];
    float w10 = W[(k0 + 8) * Hn + nc];
    float w11 = W[(k0 + 9) * Hn + nc];

    float h00 = bf16_hi_part(w00), h01 = bf16_hi_part(w01);
    float h10 = bf16_hi_part(w10), h11 = bf16_hi_part(w11);

    uint4 f;
    f.x = pack_bf16(w00, w01);               // hi reg0
    f.y = pack_bf16(w10, w11);               // hi reg1
    f.z = pack_bf16(w00 - h00, w01 - h01);   // lo reg0
    f.w = pack_bf16(w10 - h10, w11 - h11);   // lo reg1
    g_bfrag[idx] = f;
}

// ---------------------------------------------------------------------------
// Projection GEMM via mma.sync bf16 3-product split.
// Grid: 2048 blocks x 256 threads. Block tile M=128, N=192.
// Warp grid: 4 along M (warp M=32 -> 2 mtiles of 16), 2 along N (warp N=96
// -> 12 ntiles of 8). K streamed in 12 chunks of 32 (2 k-tiles), 2-stage smem.
// smem A rows have 80B stride -> conflict-free ldmatrix.
// ---------------------------------------------------------------------------
__global__ __launch_bounds__(256) void proj_mma_kernel(const float* __restrict__ x) {
    __shared__ uint32_t sA[2][2][128 * 20];   // [stage][hi/lo][row*20 + colu32]

    const int tid = threadIdx.x;
    const int wid = tid >> 5;
    const int lane = tid & 31;
    const int row0 = blockIdx.x * 128;

    const int wm = (wid & 3) * 32;            // warp M offset within block
    const int nw = wid >> 2;                  // 0/1 -> N half

    // x staging: thread owns row tid/2, 16 cols starting at (tid&1)*16
    const int xr = tid >> 1;
    const int xc = (tid & 1) * 16;
    const float* xrow = x + (size_t)(row0 + xr) * Cn + xc;

    float4 v[4];
#pragma unroll
    for (int j = 0; j < 4; ++j) v[j] = __ldg((const float4*)xrow + j);

    // store chunk 0 into stage 0
    {
        const int base = xr * 20 + xc / 2;
#pragma unroll
        for (int j = 0; j < 4; ++j) {
            float hx = bf16_hi_part(v[j].x), hy = bf16_hi_part(v[j].y);
            float hz = bf16_hi_part(v[j].z), hw = bf16_hi_part(v[j].w);
            sA[0][0][base + 2 * j + 0] = pack_bf16(v[j].x, v[j].y);
            sA[0][0][base + 2 * j + 1] = pack_bf16(v[j].z, v[j].w);
            sA[0][1][base + 2 * j + 0] = pack_bf16(v[j].x - hx, v[j].y - hy);
            sA[0][1][base + 2 * j + 1] = pack_bf16(v[j].z - hz, v[j].w - hw);
        }
    }
    __syncthreads();

    float acc[2][12][4];
#pragma unroll
    for (int mt = 0; mt < 2; ++mt)
#pragma unroll
        for (int nt = 0; nt < 12; ++nt)
#pragma unroll
            for (int e = 0; e < 4; ++e) acc[mt][nt][e] = 0.f;

    // ldmatrix lane addressing: row = lane&15, kcol8 = (lane>>4)*8
    const int lrow = lane & 15;
    const int lk8 = (lane >> 4) * 8;

    for (int c = 0; c < 12; ++c) {
        const int st = c & 1;

        if (c < 11) {
            const float* nx = xrow + (c + 1) * 32;
#pragma unroll
            for (int j = 0; j < 4; ++j) v[j] = __ldg((const float4*)nx + j);
        }

        const uint32_t aHiBase = smem_u32(&sA[st][0][0]);
        const uint32_t aLoBase = smem_u32(&sA[st][1][0]);

#pragma unroll
        for (int kt = 0; kt < 2; ++kt) {
            uint32_t ahi[2][4], alo[2][4];
#pragma unroll
            for (int mt = 0; mt < 2; ++mt) {
                uint32_t off = (uint32_t)((wm + mt * 16 + lrow) * 80 +
                                          (kt * 16 + lk8) * 2);
                ldmatrix_x4(ahi[mt], aHiBase + off);
                ldmatrix_x4(alo[mt], aLoBase + off);
            }
            const uint4* bp = g_bfrag + (size_t)(((c * 2 + kt) * 24 + nw * 12) * 32 + lane);
#pragma unroll
            for (int nt = 0; nt < 12; ++nt) {
                uint4 bf = __ldg(bp + nt * 32);
#pragma unroll
                for (int mt = 0; mt < 2; ++mt) {
                    mma_bf16(acc[mt][nt], ahi[mt], bf.x, bf.y);   // hi*hi
                    mma_bf16(acc[mt][nt], ahi[mt], bf.z, bf.w);   // hi*lo
                    mma_bf16(acc[mt][nt], alo[mt], bf.x, bf.y);   // lo*hi
                }
            }
        }

        if (c < 11) {
            __syncthreads();   // all warps done reading stage st^1 (chunk c-1)
            const int base = xr * 20 + xc / 2;
            const int so = st ^ 1;
#pragma unroll
            for (int j = 0; j < 4; ++j) {
                float hx = bf16_hi_part(v[j].x), hy = bf16_hi_part(v[j].y);
                float hz = bf16_hi_part(v[j].z), hw = bf16_hi_part(v[j].w);
                sA[so][0][base + 2 * j + 0] = pack_bf16(v[j].x, v[j].y);
                sA[so][0][base + 2 * j + 1] = pack_bf16(v[j].z, v[j].w);
                sA[so][1][base + 2 * j + 0] = pack_bf16(v[j].x - hx, v[j].y - hy);
                sA[so][1][base + 2 * j + 1] = pack_bf16(v[j].z - hz, v[j].w - hw);
            }
            __syncthreads();
        }
    }

    // Epilogue: C frag -> rows lane/4, lane/4+8; cols (lane&3)*2,+1
#pragma unroll
    for (int mt = 0; mt < 2; ++mt) {
#pragma unroll
        for (int nt = 0; nt < 12; ++nt) {
            int n = nw * 96 + nt * 8 + (lane & 3) * 2;
            float* dst = (n < 64) ? g_q : (n < 128) ? g_k : g_v;
            int ncol = n & 63;
            size_t r0g = (size_t)(row0 + wm + mt * 16 + (lane >> 2));
            *(float2*)&dst[r0g * Hn + ncol] =
                make_float2(acc[mt][nt][0], acc[mt][nt][1]);
            *(float2*)&dst[(r0g + 8) * Hn + ncol] =
                make_float2(acc[mt][nt][2], acc[mt][nt][3]);
        }
    }
}

// ---------------------------------------------------------------------------
// Flash-attention (causal, online softmax) — unchanged from R1 (passing).
// ---------------------------------------------------------------------------
#define SQ_OFF   0
#define SK_OFF   (64 * 64)
#define SV_OFF   (SK_OFF + 64 * 65)
#define SS_OFF   (SV_OFF + 64 * 65)
#define SM_OFF   (SS_OFF + 64 * 65)
#define SL_OFF   (SM_OFF + 64)
#define SF_OFF   (SL_OFF + 64)
#define SMEM_FLOATS (SF_OFF + 64)

__global__ __launch_bounds__(256) void attn_kernel(float* __restrict__ out)
{
    extern __shared__ float sm[];
    float* sQ   = sm + SQ_OFF;
    float* sK   = sm + SK_OFF;
    float* sV   = sm + SV_OFF;
    float* sS   = sm + SS_OFF;
    float* sM   = sm + SM_OFF;
    float* sL   = sm + SL_OFF;
    float* sFac = sm + SF_OFF;

    const int tid  = threadIdx.x;
    const int qt   = blockIdx.x;
    const int b    = blockIdx.y;
    const int lane = tid & 31;
    const int qg   = tid >> 5;
    const int qbase = (b * Tn + qt * 64) * Hn;

#pragma unroll
    for (int j = 0; j < 16; ++j) {
        int idx = tid + j * 256;
        sQ[idx] = g_q[qbase + idx] * 0.125f;
    }
    if (tid < 64) { sM[tid] = -1e30f; sL[tid] = 0.f; }

    float acc[8][2];
#pragma unroll
    for (int i = 0; i < 8; ++i) { acc[i][0] = 0.f; acc[i][1] = 0.f; }

    for (int kt = 0; kt <= qt; ++kt) {
        __syncthreads();
        const int kbase = (b * Tn + kt * 64) * Hn;
#pragma unroll
        for (int j = 0; j < 16; ++j) {
            int idx = tid + j * 256;
            int r = idx >> 6, h = idx & 63;
            sK[r * 65 + h] = g_k[kbase + idx];
            sV[r * 65 + h] = g_v[kbase + idx];
        }
        __syncthreads();

        float s0[8], s1[8];
#pragma unroll
        for (int i = 0; i < 8; ++i) { s0[i] = 0.f; s1[i] = 0.f; }
#pragma unroll 8
        for (int h = 0; h < 64; ++h) {
            float k0 = sK[lane * 65 + h];
            float k1 = sK[(lane + 32) * 65 + h];
#pragma unroll
            for (int i = 0; i < 8; ++i) {
                float qv = sQ[(qg * 8 + i) * 64 + h];
                s0[i] += qv * k0;
                s1[i] += qv * k1;
            }
        }

        const bool diag = (kt == qt);
#pragma unroll
        for (int i = 0; i < 8; ++i) {
            int r = qg * 8 + i;
            float v0 = s0[i], v1 = s1[i];
            if (diag) {
                if (lane > r)      v0 = -1e30f;
                if (lane + 32 > r) v1 = -1e30f;
            }
            sS[r * 65 + lane]      = v0;
            sS[r * 65 + lane + 32] = v1;
        }
        __syncthreads();

        if (tid < 64) {
            int row = tid;
            float mo = sM[row];
            float mt = mo;
#pragma unroll 8
            for (int k = 0; k < 64; ++k)
                mt = fmaxf(mt, sS[row * 65 + k]);
            float fac = __expf(mo - mt);
            float sum = 0.f;
#pragma unroll 8
            for (int k = 0; k < 64; ++k) {
                float p = __expf(sS[row * 65 + k] - mt);
                sS[row * 65 + k] = p;
                sum += p;
            }
            sL[row]   = sL[row] * fac + sum;
            sM[row]   = mt;
            sFac[row] = fac;
        }
        __syncthreads();

#pragma unroll
        for (int i = 0; i < 8; ++i) {
            float f = sFac[qg * 8 + i];
            acc[i][0] *= f;
            acc[i][1] *= f;
        }
#pragma unroll 8
        for (int k = 0; k < 64; ++k) {
            float v0 = sV[k * 65 + lane];
            float v1 = sV[k * 65 + lane + 32];
#pragma unroll
            for (int i = 0; i < 8; ++i) {
                float p = sS[(qg * 8 + i) * 65 + k];
                acc[i][0] += p * v0;
                acc[i][1] += p * v1;
            }
        }
    }

#pragma unroll
    for (int i = 0; i < 8; ++i) {
        int r = qg * 8 + i;
        float inv = 1.0f / sL[r];
        out[qbase + r * Hn + lane]      = acc[i][0] * inv;
        out[qbase + r * Hn + lane + 32] = acc[i][1] * inv;
    }
}

// ---------------------------------------------------------------------------
extern "C" void kernel_launch(void* const* d_in, const int* in_sizes, int n_in,
                              void* d_out, int out_size)
{
    const float* x  = (const float*)d_in[0];
    const float* Wk = (const float*)d_in[1];
    const float* Wq = (const float*)d_in[2];
    const float* Wv = (const float*)d_in[3];
    float* out = (float*)d_out;

    prep_w_kernel<<<(24 * 24 * 32 + 255) / 256, 256>>>(Wk, Wq, Wv);

    proj_mma_kernel<<<(Bn * Tn) / 128, 256>>>(x);

    const int smem_bytes = SMEM_FLOATS * (int)sizeof(float);
    cudaFuncSetAttribute(attn_kernel,
                         cudaFuncAttributeMaxDynamicSharedMemorySize, smem_bytes);
    attn_kernel<<<dim3(Tn / 64, Bn), 256, smem_bytes>>>(out);
}

// round 6
// speedup vs baseline: 2.2845x; 1.5382x over previous
#include <cuda_runtime.h>
#include <cuda_bf16.h>
#include <cstdint>

#define Bn 1024
#define Tn 256
#define Cn 384
#define Hn 64

__device__ float g_q[Bn * Tn * Hn];
__device__ float g_k[Bn * Tn * Hn];
__device__ float g_v[Bn * Tn * Hn];

// Pre-packed B fragments for mma.sync.m16n8k16 (row.col):
// index ((kt*24 + nt)*32 + lane) -> {bhi_r0, bhi_r1, blo_r0, blo_r1}
__device__ uint4 g_bfrag[24 * 24 * 32];

// ---------------------------------------------------------------------------
__device__ __forceinline__ uint32_t smem_u32(const void* p) {
    uint32_t a;
    asm("{ .reg .u64 t; cvta.to.shared.u64 t, %1; cvt.u32.u64 %0, t; }" : "=r"(a) : "l"(p));
    return a;
}
__device__ __forceinline__ uint32_t pack_bf16(float a, float b) {
    uint32_t lo = __bfloat16_as_ushort(__float2bfloat16_rn(a));
    uint32_t hi = __bfloat16_as_ushort(__float2bfloat16_rn(b));
    return lo | (hi << 16);
}
__device__ __forceinline__ float bf16_hi_part(float v) {
    return __bfloat162float(__float2bfloat16_rn(v));
}
__device__ __forceinline__ void mma_bf16(float* c, const uint32_t* a,
                                         uint32_t b0, uint32_t b1) {
    asm volatile(
        "mma.sync.aligned.m16n8k16.row.col.f32.bf16.bf16.f32 "
        "{%0,%1,%2,%3}, {%4,%5,%6,%7}, {%8,%9}, {%0,%1,%2,%3};"
        : "+f"(c[0]), "+f"(c[1]), "+f"(c[2]), "+f"(c[3])
        : "r"(a[0]), "r"(a[1]), "r"(a[2]), "r"(a[3]), "r"(b0), "r"(b1));
}
__device__ __forceinline__ void ldmatrix_x4(uint32_t* r, uint32_t addr) {
    asm volatile(
        "ldmatrix.sync.aligned.m8n8.x4.shared.b16 {%0,%1,%2,%3}, [%4];"
        : "=r"(r[0]), "=r"(r[1]), "=r"(r[2]), "=r"(r[3]) : "r"(addr));
}
__device__ __forceinline__ void ldmatrix_x4_trans(uint32_t* r, uint32_t addr) {
    asm volatile(
        "ldmatrix.sync.aligned.m8n8.x4.trans.shared.b16 {%0,%1,%2,%3}, [%4];"
        : "=r"(r[0]), "=r"(r[1]), "=r"(r[2]), "=r"(r[3]) : "r"(addr));
}
#define CP_ASYNC16(dst, src) \
    asm volatile("cp.async.cg.shared.global [%0], [%1], 16;" :: "r"(dst), "l"(src))
#define CP_COMMIT() asm volatile("cp.async.commit_group;" ::: "memory")
#define CP_WAIT(n)  asm volatile("cp.async.wait_group %0;" :: "n"(n) : "memory")

// ---------------------------------------------------------------------------
// Weight prep (unchanged): bf16 hi/lo B-fragments in mma.sync register layout.
// ---------------------------------------------------------------------------
__global__ void prep_w_kernel(const float* __restrict__ Wk,
                              const float* __restrict__ Wq,
                              const float* __restrict__ Wv) {
    int idx = blockIdx.x * 256 + threadIdx.x;
    if (idx >= 24 * 24 * 32) return;
    int lane = idx & 31;
    int nt = (idx >> 5) % 24;
    int kt = (idx >> 5) / 24;

    int n = nt * 8 + (lane >> 2);
    int k0 = kt * 16 + (lane & 3) * 2;
    const float* W = (n < 64) ? Wq : (n < 128) ? Wk : Wv;
    int nc = n & 63;

    float w00 = W[(k0 + 0) * Hn + nc];
    float w01 = W[(k0 + 1) * Hn + nc];
    float w10 = W[(k0 + 8) * Hn + nc];
    float w11 = W[(k0 + 9) * Hn + nc];

    float h00 = bf16_hi_part(w00), h01 = bf16_hi_part(w01);
    float h10 = bf16_hi_part(w10), h11 = bf16_hi_part(w11);

    uint4 f;
    f.x = pack_bf16(w00, w01);
    f.y = pack_bf16(w10, w11);
    f.z = pack_bf16(w00 - h00, w01 - h01);
    f.w = pack_bf16(w10 - h10, w11 - h11);
    g_bfrag[idx] = f;
}

// ---------------------------------------------------------------------------
// Projection GEMM: B fragments staged via cp.async double-buffered smem.
// Block tile M=128, N=192; 8 warps (4 x M, 2 x N). 12 k-chunks of 32.
// Dynamic smem: sA 40960B (2 stages x hi/lo x 128x20 u32) + sB 2 x 24576B.
// ---------------------------------------------------------------------------
#define SB_OFF_U8 40960
#define PROJ_SMEM (40960 + 2 * 24576)

__global__ __launch_bounds__(256) void proj_mma_kernel(const float* __restrict__ x) {
    extern __shared__ __align__(16) char psm[];
    uint32_t* sA = (uint32_t*)psm;                    // [(st*2+hilo)*2560 + idx]
    uint4*    sB = (uint4*)(psm + SB_OFF_U8);         // [st*1536 + frag]

    const int tid = threadIdx.x;
    const int wid = tid >> 5;
    const int lane = tid & 31;
    const int row0 = blockIdx.x * 128;

    const int wm = (wid & 3) * 32;
    const int nw = wid >> 2;

    const int xr = tid >> 1;
    const int xc = (tid & 1) * 16;
    const float* xrow = x + (size_t)(row0 + xr) * Cn + xc;
    const uint4* gB = g_bfrag;

    // prologue: B chunk 0 via cp.async, A chunk 0 via registers
#pragma unroll
    for (int j = 0; j < 6; ++j)
        CP_ASYNC16(smem_u32(&sB[tid + j * 256]), gB + tid + j * 256);
    CP_COMMIT();

    float4 v[4];
#pragma unroll
    for (int j = 0; j < 4; ++j) v[j] = __ldg((const float4*)xrow + j);
    {
        const int base = xr * 20 + xc / 2;
#pragma unroll
        for (int j = 0; j < 4; ++j) {
            float hx = bf16_hi_part(v[j].x), hy = bf16_hi_part(v[j].y);
            float hz = bf16_hi_part(v[j].z), hw = bf16_hi_part(v[j].w);
            sA[base + 2 * j + 0]        = pack_bf16(v[j].x, v[j].y);
            sA[base + 2 * j + 1]        = pack_bf16(v[j].z, v[j].w);
            sA[2560 + base + 2 * j + 0] = pack_bf16(v[j].x - hx, v[j].y - hy);
            sA[2560 + base + 2 * j + 1] = pack_bf16(v[j].z - hz, v[j].w - hw);
        }
    }

    float acc[2][12][4];
#pragma unroll
    for (int mt = 0; mt < 2; ++mt)
#pragma unroll
        for (int nt = 0; nt < 12; ++nt)
#pragma unroll
            for (int e = 0; e < 4; ++e) acc[mt][nt][e] = 0.f;

    const int lrow = lane & 15;
    const int lk8 = (lane >> 4) * 8;

    for (int c = 0; c < 12; ++c) {
        const int st = c & 1;

        if (c < 11) {
#pragma unroll
            for (int j = 0; j < 6; ++j)
                CP_ASYNC16(smem_u32(&sB[(st ^ 1) * 1536 + tid + j * 256]),
                           gB + (c + 1) * 1536 + tid + j * 256);
            CP_COMMIT();
            const float* nx = xrow + (c + 1) * 32;
#pragma unroll
            for (int j = 0; j < 4; ++j) v[j] = __ldg((const float4*)nx + j);
        }
        if (c < 11) { CP_WAIT(1); } else { CP_WAIT(0); }
        __syncthreads();   // B_c arrived + A_c stores visible + stage free

        const uint32_t aHiBase = smem_u32(&sA[(st * 2 + 0) * 2560]);
        const uint32_t aLoBase = smem_u32(&sA[(st * 2 + 1) * 2560]);

#pragma unroll
        for (int kt = 0; kt < 2; ++kt) {
            uint32_t ahi[2][4], alo[2][4];
#pragma unroll
            for (int mt = 0; mt < 2; ++mt) {
                uint32_t off = (uint32_t)((wm + mt * 16 + lrow) * 80 +
                                          (kt * 16 + lk8) * 2);
                ldmatrix_x4(ahi[mt], aHiBase + off);
                ldmatrix_x4(alo[mt], aLoBase + off);
            }
            const uint4* bp = sB + (st * 1536 + ((kt * 24 + nw * 12) * 32 + lane));
#pragma unroll
            for (int nt = 0; nt < 12; ++nt) {
                uint4 bf = bp[nt * 32];
#pragma unroll
                for (int mt = 0; mt < 2; ++mt) {
                    mma_bf16(acc[mt][nt], ahi[mt], bf.x, bf.y);   // hi*hi
                    mma_bf16(acc[mt][nt], ahi[mt], bf.z, bf.w);   // hi*lo
                    mma_bf16(acc[mt][nt], alo[mt], bf.x, bf.y);   // lo*hi
                }
            }
        }

        if (c < 11) {
            __syncthreads();   // all warps done with mma(c) -> sA[st^1] free
            const int base = (st ^ 1) * 2 * 2560 + xr * 20 + xc / 2;
#pragma unroll
            for (int j = 0; j < 4; ++j) {
                float hx = bf16_hi_part(v[j].x), hy = bf16_hi_part(v[j].y);
                float hz = bf16_hi_part(v[j].z), hw = bf16_hi_part(v[j].w);
                sA[base + 2 * j + 0]        = pack_bf16(v[j].x, v[j].y);
                sA[base + 2 * j + 1]        = pack_bf16(v[j].z, v[j].w);
                sA[2560 + base + 2 * j + 0] = pack_bf16(v[j].x - hx, v[j].y - hy);
                sA[2560 + base + 2 * j + 1] = pack_bf16(v[j].z - hz, v[j].w - hw);
            }
        }
    }

#pragma unroll
    for (int mt = 0; mt < 2; ++mt) {
#pragma unroll
        for (int nt = 0; nt < 12; ++nt) {
            int n = nw * 96 + nt * 8 + (lane & 3) * 2;
            float* dst = (n < 64) ? g_q : (n < 128) ? g_k : g_v;
            int ncol = n & 63;
            size_t r0g = (size_t)(row0 + wm + mt * 16 + (lane >> 2));
            *(float2*)&dst[r0g * Hn + ncol] =
                make_float2(acc[mt][nt][0], acc[mt][nt][1]);
            *(float2*)&dst[(r0g + 8) * Hn + ncol] =
                make_float2(acc[mt][nt][2], acc[mt][nt][3]);
        }
    }
}

// ---------------------------------------------------------------------------
// Flash-attention via mma.sync (FA2-style, register-resident softmax).
// Grid: (4, 1024), 128 threads. Warp w owns q rows w*16..+15 of a 64-row tile.
// smem: K/V tiles hi/lo bf16, 72-elem (144B) row stride -> conflict-free ldmatrix.
// ---------------------------------------------------------------------------
__global__ __launch_bounds__(128) void attn_mma_kernel(float* __restrict__ out)
{
    __shared__ __align__(16) uint16_t sKhi[64 * 72], sKlo[64 * 72];
    __shared__ __align__(16) uint16_t sVhi[64 * 72], sVlo[64 * 72];

    const int tid = threadIdx.x;
    const int wid = tid >> 5;
    const int lane = tid & 31;
    const int qt = blockIdx.x;
    const int b = blockIdx.y;
    const int qb = wid * 16;
    const int ri = lane & 7;
    const int tq = lane >> 3;    // ldmatrix address group 0..3

    const size_t qbase = (size_t)(b * Tn + qt * 64) * Hn;

    // --- Stage Q (scaled) into sVhi/sVlo, load A-fragments, keep in regs ---
    uint32_t qhi[4][4], qlo[4][4];
    {
#pragma unroll
        for (int j = 0; j < 8; ++j) {
            int idx4 = tid + j * 128;
            int row = idx4 >> 4, h = (idx4 & 15) * 4;
            float4 q4 = __ldg((const float4*)(g_q + qbase) + idx4);
            q4.x *= 0.125f; q4.y *= 0.125f; q4.z *= 0.125f; q4.w *= 0.125f;
            float hx = bf16_hi_part(q4.x), hy = bf16_hi_part(q4.y);
            float hz = bf16_hi_part(q4.z), hw = bf16_hi_part(q4.w);
            uint32_t* ph = (uint32_t*)&sVhi[row * 72 + h];
            uint32_t* pl = (uint32_t*)&sVlo[row * 72 + h];
            ph[0] = pack_bf16(q4.x, q4.y); ph[1] = pack_bf16(q4.z, q4.w);
            pl[0] = pack_bf16(q4.x - hx, q4.y - hy);
            pl[1] = pack_bf16(q4.z - hz, q4.w - hw);
        }
        __syncthreads();
#pragma unroll
        for (int kt16 = 0; kt16 < 4; ++kt16) {
            // A-frag x4: t0 rows+0/h+0, t1 rows+8/h+0, t2 rows+0/h+8, t3 rows+8/h+8
            int row = qb + (tq & 1) * 8 + ri;
            int h = kt16 * 16 + (tq >> 1) * 8;
            ldmatrix_x4(qhi[kt16], smem_u32(&sVhi[row * 72 + h]));
            ldmatrix_x4(qlo[kt16], smem_u32(&sVlo[row * 72 + h]));
        }
    }

    float o[8][4];
#pragma unroll
    for (int nt = 0; nt < 8; ++nt)
#pragma unroll
        for (int e = 0; e < 4; ++e) o[nt][e] = 0.f;
    float m0 = -1e30f, m1 = -1e30f, l0 = 0.f, l1 = 0.f;

    const int r_lo = lane >> 2;          // local row within m16 (and +8)
    const int cb = (lane & 3) * 2;       // accum col base within n8

    for (int kt = 0; kt <= qt; ++kt) {
        __syncthreads();   // Q frags read (iter0) / previous tile's mma done
        const size_t kvbase = (size_t)(b * Tn + kt * 64) * Hn;
#pragma unroll
        for (int j = 0; j < 8; ++j) {
            int idx4 = tid + j * 128;
            int row = idx4 >> 4, h = (idx4 & 15) * 4;
            float4 k4 = __ldg((const float4*)(g_k + kvbase) + idx4);
            float4 v4 = __ldg((const float4*)(g_v + kvbase) + idx4);
            float khx = bf16_hi_part(k4.x), khy = bf16_hi_part(k4.y);
            float khz = bf16_hi_part(k4.z), khw = bf16_hi_part(k4.w);
            uint32_t* pkh = (uint32_t*)&sKhi[row * 72 + h];
            uint32_t* pkl = (uint32_t*)&sKlo[row * 72 + h];
            pkh[0] = pack_bf16(k4.x, k4.y); pkh[1] = pack_bf16(k4.z, k4.w);
            pkl[0] = pack_bf16(k4.x - khx, k4.y - khy);
            pkl[1] = pack_bf16(k4.z - khz, k4.w - khw);
            float vhx = bf16_hi_part(v4.x), vhy = bf16_hi_part(v4.y);
            float vhz = bf16_hi_part(v4.z), vhw = bf16_hi_part(v4.w);
            uint32_t* pvh = (uint32_t*)&sVhi[row * 72 + h];
            uint32_t* pvl = (uint32_t*)&sVlo[row * 72 + h];
            pvh[0] = pack_bf16(v4.x, v4.y); pvh[1] = pack_bf16(v4.z, v4.w);
            pvl[0] = pack_bf16(v4.x - vhx, v4.y - vhy);
            pvl[1] = pack_bf16(v4.z - vhz, v4.w - vhw);
        }
        __syncthreads();

        // --- S = Q K^T : 8 ntiles (krow octets) x 4 ktiles (h) x 3 split ---
        float s[8][4];
#pragma unroll
        for (int nt = 0; nt < 8; ++nt)
#pragma unroll
            for (int e = 0; e < 4; ++e) s[nt][e] = 0.f;

#pragma unroll
        for (int kt16 = 0; kt16 < 4; ++kt16) {
#pragma unroll
            for (int np = 0; np < 4; ++np) {
                // B-frag x4 (non-trans; K is [n][k] = B col-major):
                // t0 (kr+0,h+0) t1 (kr+0,h+8) t2 (kr+8,h+0) t3 (kr+8,h+8)
                int krow = np * 16 + (tq >> 1) * 8 + ri;
                int h = kt16 * 16 + (tq & 1) * 8;
                uint32_t kh[4], kl[4];
                ldmatrix_x4(kh, smem_u32(&sKhi[krow * 72 + h]));
                ldmatrix_x4(kl, smem_u32(&sKlo[krow * 72 + h]));
                mma_bf16(s[2 * np],     qhi[kt16], kh[0], kh[1]);
                mma_bf16(s[2 * np],     qhi[kt16], kl[0], kl[1]);
                mma_bf16(s[2 * np],     qlo[kt16], kh[0], kh[1]);
                mma_bf16(s[2 * np + 1], qhi[kt16], kh[2], kh[3]);
                mma_bf16(s[2 * np + 1], qhi[kt16], kl[2], kl[3]);
                mma_bf16(s[2 * np + 1], qlo[kt16], kh[2], kh[3]);
            }
        }

        // --- causal mask (diag tile only) ---
        if (kt == qt) {
            int r0 = qb + r_lo, r1 = r0 + 8;
#pragma unroll
            for (int nt = 0; nt < 8; ++nt) {
                int kc = nt * 8 + cb;
                if (kc > r0)     s[nt][0] = -1e30f;
                if (kc + 1 > r0) s[nt][1] = -1e30f;
                if (kc > r1)     s[nt][2] = -1e30f;
                if (kc + 1 > r1) s[nt][3] = -1e30f;
            }
        }

        // --- online softmax, register-resident ---
        float mx0 = -1e30f, mx1 = -1e30f;
#pragma unroll
        for (int nt = 0; nt < 8; ++nt) {
            mx0 = fmaxf(mx0, fmaxf(s[nt][0], s[nt][1]));
            mx1 = fmaxf(mx1, fmaxf(s[nt][2], s[nt][3]));
        }
        mx0 = fmaxf(mx0, __shfl_xor_sync(0xffffffffu, mx0, 1));
        mx0 = fmaxf(mx0, __shfl_xor_sync(0xffffffffu, mx0, 2));
        mx1 = fmaxf(mx1, __shfl_xor_sync(0xffffffffu, mx1, 1));
        mx1 = fmaxf(mx1, __shfl_xor_sync(0xffffffffu, mx1, 2));
        float mn0 = fmaxf(m0, mx0), mn1 = fmaxf(m1, mx1);
        float fac0 = __expf(m0 - mn0), fac1 = __expf(m1 - mn1);
        m0 = mn0; m1 = mn1;

        float sum0 = 0.f, sum1 = 0.f;
#pragma unroll
        for (int nt = 0; nt < 8; ++nt) {
            s[nt][0] = __expf(s[nt][0] - mn0);
            s[nt][1] = __expf(s[nt][1] - mn0);
            s[nt][2] = __expf(s[nt][2] - mn1);
            s[nt][3] = __expf(s[nt][3] - mn1);
            sum0 += s[nt][0] + s[nt][1];
            sum1 += s[nt][2] + s[nt][3];
        }
        sum0 += __shfl_xor_sync(0xffffffffu, sum0, 1);
        sum0 += __shfl_xor_sync(0xffffffffu, sum0, 2);
        sum1 += __shfl_xor_sync(0xffffffffu, sum1, 1);
        sum1 += __shfl_xor_sync(0xffffffffu, sum1, 2);
        l0 = l0 * fac0 + sum0;
        l1 = l1 * fac1 + sum1;

#pragma unroll
        for (int nt = 0; nt < 8; ++nt) {
            o[nt][0] *= fac0; o[nt][1] *= fac0;
            o[nt][2] *= fac1; o[nt][3] *= fac1;
        }

        // --- O += P V : P from s regs (accum layout == A-frag layout) ---
#pragma unroll
        for (int kv = 0; kv < 4; ++kv) {
            uint32_t pa_hi[4], pa_lo[4];
            {
                float p00 = s[2 * kv][0],     p01 = s[2 * kv][1];
                float p02 = s[2 * kv][2],     p03 = s[2 * kv][3];
                float p10 = s[2 * kv + 1][0], p11 = s[2 * kv + 1][1];
                float p12 = s[2 * kv + 1][2], p13 = s[2 * kv + 1][3];
                pa_hi[0] = pack_bf16(p00, p01);
                pa_hi[1] = pack_bf16(p02, p03);
                pa_hi[2] = pack_bf16(p10, p11);
                pa_hi[3] = pack_bf16(p12, p13);
                pa_lo[0] = pack_bf16(p00 - bf16_hi_part(p00), p01 - bf16_hi_part(p01));
                pa_lo[1] = pack_bf16(p02 - bf16_hi_part(p02), p03 - bf16_hi_part(p03));
                pa_lo[2] = pack_bf16(p10 - bf16_hi_part(p10), p11 - bf16_hi_part(p11));
                pa_lo[3] = pack_bf16(p12 - bf16_hi_part(p12), p13 - bf16_hi_part(p13));
            }
#pragma unroll
            for (int np = 0; np < 4; ++np) {
                // B-frag x4 trans (V is [k][n] row-major):
                // t0 (kr+0,h+0) t1 (kr+8,h+0) t2 (kr+0,h+8) t3 (kr+8,h+8)
                int krow = kv * 16 + (tq & 1) * 8 + ri;
                int h = np * 16 + (tq >> 1) * 8;
                uint32_t vh[4], vl[4];
                ldmatrix_x4_trans(vh, smem_u32(&sVhi[krow * 72 + h]));
                ldmatrix_x4_trans(vl, smem_u32(&sVlo[krow * 72 + h]));
                mma_bf16(o[2 * np],     pa_hi, vh[0], vh[1]);
                mma_bf16(o[2 * np],     pa_hi, vl[0], vl[1]);
                mma_bf16(o[2 * np],     pa_lo, vh[0], vh[1]);
                mma_bf16(o[2 * np + 1], pa_hi, vh[2], vh[3]);
                mma_bf16(o[2 * np + 1], pa_hi, vl[2], vl[3]);
                mma_bf16(o[2 * np + 1], pa_lo, vh[2], vh[3]);
            }
        }
    }

    // --- normalize + store ---
    float inv0 = 1.0f / l0, inv1 = 1.0f / l1;
    size_t gr0 = qbase + (size_t)(qb + r_lo) * Hn;
    size_t gr1 = gr0 + 8 * Hn;
#pragma unroll
    for (int nt = 0; nt < 8; ++nt) {
        int col = nt * 8 + cb;
        *(float2*)&out[gr0 + col] = make_float2(o[nt][0] * inv0, o[nt][1] * inv0);
        *(float2*)&out[gr1 + col] = make_float2(o[nt][2] * inv1, o[nt][3] * inv1);
    }
}

// ---------------------------------------------------------------------------
extern "C" void kernel_launch(void* const* d_in, const int* in_sizes, int n_in,
                              void* d_out, int out_size)
{
    const float* x  = (const float*)d_in[0];
    const float* Wk = (const float*)d_in[1];
    const float* Wq = (const float*)d_in[2];
    const float* Wv = (const float*)d_in[3];
    float* out = (float*)d_out;

    prep_w_kernel<<<(24 * 24 * 32 + 255) / 256, 256>>>(Wk, Wq, Wv);

    cudaFuncSetAttribute(proj_mma_kernel,
                         cudaFuncAttributeMaxDynamicSharedMemorySize, PROJ_SMEM);
    proj_mma_kernel<<<(Bn * Tn) / 128, 256, PROJ_SMEM>>>(x);

    attn_mma_kernel<<<dim3(Tn / 64, Bn), 128>>>(out);
}

// round 7
// speedup vs baseline: 2.3195x; 1.0153x over previous
#include <cuda_runtime.h>
#include <cuda_bf16.h>
#include <cstdint>

#define Bn 1024
#define Tn 256
#define Cn 384
#define Hn 64

__device__ float g_q[Bn * Tn * Hn];
// K/V pre-split bf16 hi/lo, packed 2 cols per uint32: idx = row*32 + col/2
__device__ __align__(16) uint32_t g_khi[Bn * Tn * 32];
__device__ __align__(16) uint32_t g_klo[Bn * Tn * 32];
__device__ __align__(16) uint32_t g_vhi[Bn * Tn * 32];
__device__ __align__(16) uint32_t g_vlo[Bn * Tn * 32];

// Pre-packed B fragments for mma.sync.m16n8k16 (row.col)
__device__ uint4 g_bfrag[24 * 24 * 32];

// ---------------------------------------------------------------------------
__device__ __forceinline__ uint32_t smem_u32(const void* p) {
    uint32_t a;
    asm("{ .reg .u64 t; cvta.to.shared.u64 t, %1; cvt.u32.u64 %0, t; }" : "=r"(a) : "l"(p));
    return a;
}
__device__ __forceinline__ uint32_t pack_bf16(float a, float b) {
    uint32_t lo = __bfloat16_as_ushort(__float2bfloat16_rn(a));
    uint32_t hi = __bfloat16_as_ushort(__float2bfloat16_rn(b));
    return lo | (hi << 16);
}
__device__ __forceinline__ float bf16_hi_part(float v) {
    return __bfloat162float(__float2bfloat16_rn(v));
}
__device__ __forceinline__ void mma_bf16(float* c, const uint32_t* a,
                                         uint32_t b0, uint32_t b1) {
    asm volatile(
        "mma.sync.aligned.m16n8k16.row.col.f32.bf16.bf16.f32 "
        "{%0,%1,%2,%3}, {%4,%5,%6,%7}, {%8,%9}, {%0,%1,%2,%3};"
        : "+f"(c[0]), "+f"(c[1]), "+f"(c[2]), "+f"(c[3])
        : "r"(a[0]), "r"(a[1]), "r"(a[2]), "r"(a[3]), "r"(b0), "r"(b1));
}
__device__ __forceinline__ void ldmatrix_x4(uint32_t* r, uint32_t addr) {
    asm volatile(
        "ldmatrix.sync.aligned.m8n8.x4.shared.b16 {%0,%1,%2,%3}, [%4];"
        : "=r"(r[0]), "=r"(r[1]), "=r"(r[2]), "=r"(r[3]) : "r"(addr));
}
__device__ __forceinline__ void ldmatrix_x4_trans(uint32_t* r, uint32_t addr) {
    asm volatile(
        "ldmatrix.sync.aligned.m8n8.x4.trans.shared.b16 {%0,%1,%2,%3}, [%4];"
        : "=r"(r[0]), "=r"(r[1]), "=r"(r[2]), "=r"(r[3]) : "r"(addr));
}
#define CP_ASYNC16(dst, src) \
    asm volatile("cp.async.cg.shared.global [%0], [%1], 16;" :: "r"(dst), "l"(src))
#define CP_COMMIT() asm volatile("cp.async.commit_group;" ::: "memory")
#define CP_WAIT(n)  asm volatile("cp.async.wait_group %0;" :: "n"(n) : "memory")

// ---------------------------------------------------------------------------
// Weight prep (unchanged)
// ---------------------------------------------------------------------------
__global__ void prep_w_kernel(const float* __restrict__ Wk,
                              const float* __restrict__ Wq,
                              const float* __restrict__ Wv) {
    int idx = blockIdx.x * 256 + threadIdx.x;
    if (idx >= 24 * 24 * 32) return;
    int lane = idx & 31;
    int nt = (idx >> 5) % 24;
    int kt = (idx >> 5) / 24;

    int n = nt * 8 + (lane >> 2);
    int k0 = kt * 16 + (lane & 3) * 2;
    const float* W = (n < 64) ? Wq : (n < 128) ? Wk : Wv;
    int nc = n & 63;

    float w00 = W[(k0 + 0) * Hn + nc];
    float w01 = W[(k0 + 1) * Hn + nc];
    float w10 = W[(k0 + 8) * Hn + nc];
    float w11 = W[(k0 + 9) * Hn + nc];

    float h00 = bf16_hi_part(w00), h01 = bf16_hi_part(w01);
    float h10 = bf16_hi_part(w10), h11 = bf16_hi_part(w11);

    uint4 f;
    f.x = pack_bf16(w00, w01);
    f.y = pack_bf16(w10, w11);
    f.z = pack_bf16(w00 - h00, w01 - h01);
    f.w = pack_bf16(w10 - h10, w11 - h11);
    g_bfrag[idx] = f;
}

// ---------------------------------------------------------------------------
// Projection GEMM (mainloop identical to R6); epilogue now emits Q fp32 and
// K/V as pre-split bf16 hi/lo packed images.
// ---------------------------------------------------------------------------
#define SB_OFF_U8 40960
#define PROJ_SMEM (40960 + 2 * 24576)

__global__ __launch_bounds__(256) void proj_mma_kernel(const float* __restrict__ x) {
    extern __shared__ __align__(16) char psm[];
    uint32_t* sA = (uint32_t*)psm;
    uint4*    sB = (uint4*)(psm + SB_OFF_U8);

    const int tid = threadIdx.x;
    const int wid = tid >> 5;
    const int lane = tid & 31;
    const int row0 = blockIdx.x * 128;

    const int wm = (wid & 3) * 32;
    const int nw = wid >> 2;

    const int xr = tid >> 1;
    const int xc = (tid & 1) * 16;
    const float* xrow = x + (size_t)(row0 + xr) * Cn + xc;
    const uint4* gB = g_bfrag;

#pragma unroll
    for (int j = 0; j < 6; ++j)
        CP_ASYNC16(smem_u32(&sB[tid + j * 256]), gB + tid + j * 256);
    CP_COMMIT();

    float4 v[4];
#pragma unroll
    for (int j = 0; j < 4; ++j) v[j] = __ldg((const float4*)xrow + j);
    {
        const int base = xr * 20 + xc / 2;
#pragma unroll
        for (int j = 0; j < 4; ++j) {
            float hx = bf16_hi_part(v[j].x), hy = bf16_hi_part(v[j].y);
            float hz = bf16_hi_part(v[j].z), hw = bf16_hi_part(v[j].w);
            sA[base + 2 * j + 0]        = pack_bf16(v[j].x, v[j].y);
            sA[base + 2 * j + 1]        = pack_bf16(v[j].z, v[j].w);
            sA[2560 + base + 2 * j + 0] = pack_bf16(v[j].x - hx, v[j].y - hy);
            sA[2560 + base + 2 * j + 1] = pack_bf16(v[j].z - hz, v[j].w - hw);
        }
    }

    float acc[2][12][4];
#pragma unroll
    for (int mt = 0; mt < 2; ++mt)
#pragma unroll
        for (int nt = 0; nt < 12; ++nt)
#pragma unroll
            for (int e = 0; e < 4; ++e) acc[mt][nt][e] = 0.f;

    const int lrow = lane & 15;
    const int lk8 = (lane >> 4) * 8;

    for (int c = 0; c < 12; ++c) {
        const int st = c & 1;

        if (c < 11) {
#pragma unroll
            for (int j = 0; j < 6; ++j)
                CP_ASYNC16(smem_u32(&sB[(st ^ 1) * 1536 + tid + j * 256]),
                           gB + (c + 1) * 1536 + tid + j * 256);
            CP_COMMIT();
            const float* nx = xrow + (c + 1) * 32;
#pragma unroll
            for (int j = 0; j < 4; ++j) v[j] = __ldg((const float4*)nx + j);
        }
        if (c < 11) { CP_WAIT(1); } else { CP_WAIT(0); }
        __syncthreads();

        const uint32_t aHiBase = smem_u32(&sA[(st * 2 + 0) * 2560]);
        const uint32_t aLoBase = smem_u32(&sA[(st * 2 + 1) * 2560]);

#pragma unroll
        for (int kt = 0; kt < 2; ++kt) {
            uint32_t ahi[2][4], alo[2][4];
#pragma unroll
            for (int mt = 0; mt < 2; ++mt) {
                uint32_t off = (uint32_t)((wm + mt * 16 + lrow) * 80 +
                                          (kt * 16 + lk8) * 2);
                ldmatrix_x4(ahi[mt], aHiBase + off);
                ldmatrix_x4(alo[mt], aLoBase + off);
            }
            const uint4* bp = sB + (st * 1536 + ((kt * 24 + nw * 12) * 32 + lane));
#pragma unroll
            for (int nt = 0; nt < 12; ++nt) {
                uint4 bf = bp[nt * 32];
#pragma unroll
                for (int mt = 0; mt < 2; ++mt) {
                    mma_bf16(acc[mt][nt], ahi[mt], bf.x, bf.y);
                    mma_bf16(acc[mt][nt], ahi[mt], bf.z, bf.w);
                    mma_bf16(acc[mt][nt], alo[mt], bf.x, bf.y);
                }
            }
        }

        if (c < 11) {
            __syncthreads();
            const int base = (st ^ 1) * 2 * 2560 + xr * 20 + xc / 2;
#pragma unroll
            for (int j = 0; j < 4; ++j) {
                float hx = bf16_hi_part(v[j].x), hy = bf16_hi_part(v[j].y);
                float hz = bf16_hi_part(v[j].z), hw = bf16_hi_part(v[j].w);
                sA[base + 2 * j + 0]        = pack_bf16(v[j].x, v[j].y);
                sA[base + 2 * j + 1]        = pack_bf16(v[j].z, v[j].w);
                sA[2560 + base + 2 * j + 0] = pack_bf16(v[j].x - hx, v[j].y - hy);
                sA[2560 + base + 2 * j + 1] = pack_bf16(v[j].z - hz, v[j].w - hw);
            }
        }
    }

    // --- Epilogue: Q fp32; K/V pre-split bf16 hi/lo packed pairs ---
#pragma unroll
    for (int mt = 0; mt < 2; ++mt) {
#pragma unroll
        for (int nt = 0; nt < 12; ++nt) {
            int n = nw * 96 + nt * 8 + (lane & 3) * 2;
            size_t r0g = (size_t)(row0 + wm + mt * 16 + (lane >> 2));
            float v0 = acc[mt][nt][0], v1 = acc[mt][nt][1];
            float v2 = acc[mt][nt][2], v3 = acc[mt][nt][3];
            if (n < 64) {
                *(float2*)&g_q[r0g * Hn + n]       = make_float2(v0, v1);
                *(float2*)&g_q[(r0g + 8) * Hn + n] = make_float2(v2, v3);
            } else {
                uint32_t* hi = (n < 128) ? g_khi : g_vhi;
                uint32_t* lo = (n < 128) ? g_klo : g_vlo;
                int col2 = (n & 63) >> 1;
                float h0 = bf16_hi_part(v0), h1 = bf16_hi_part(v1);
                float h2 = bf16_hi_part(v2), h3 = bf16_hi_part(v3);
                hi[r0g * 32 + col2]       = pack_bf16(v0, v1);
                lo[r0g * 32 + col2]       = pack_bf16(v0 - h0, v1 - h1);
                hi[(r0g + 8) * 32 + col2] = pack_bf16(v2, v3);
                lo[(r0g + 8) * 32 + col2] = pack_bf16(v2 - h2, v3 - h3);
            }
        }
    }
}

// ---------------------------------------------------------------------------
// Flash-attention: 128 q-rows per block (8 warps x 16 rows), K/V tiles staged
// pre-split via cp.async, double-buffered. Arrays per stage: khi,klo,vhi,vlo,
// each 64 rows x 72-elem stride (9216B).
// ---------------------------------------------------------------------------
#define ARR_B   9216
#define STAGE_B (4 * ARR_B)
#define ATTN_SMEM (2 * STAGE_B)

__device__ __forceinline__ void stage_tile(uint32_t dst, int b, int kt, int tid) {
    size_t base_byte = (((size_t)b * Tn + kt * 64) * 64) * 2;
    const char* pkh = (const char*)g_khi + base_byte;
    const char* pkl = (const char*)g_klo + base_byte;
    const char* pvh = (const char*)g_vhi + base_byte;
    const char* pvl = (const char*)g_vlo + base_byte;
#pragma unroll
    for (int i = 0; i < 2; ++i) {
        int g = tid * 2 + i;
        uint32_t doff = (uint32_t)((g >> 3) * 144 + (g & 7) * 16);
        CP_ASYNC16(dst + 0 * ARR_B + doff, pkh + g * 16);
        CP_ASYNC16(dst + 1 * ARR_B + doff, pkl + g * 16);
        CP_ASYNC16(dst + 2 * ARR_B + doff, pvh + g * 16);
        CP_ASYNC16(dst + 3 * ARR_B + doff, pvl + g * 16);
    }
}

__global__ __launch_bounds__(256) void attn_mma_kernel(float* __restrict__ out)
{
    extern __shared__ __align__(16) char tsm[];
    const uint32_t smb = smem_u32(tsm);

    const int tid = threadIdx.x;
    const int wid = tid >> 5;
    const int lane = tid & 31;
    const int qt = blockIdx.x;        // 0..1 (128-row q tiles)
    const int b = blockIdx.y;
    const int qb = wid * 16;
    const int qbg = qt * 128 + qb;    // warp's first global q row (in batch)
    const int kmax = qt * 2 + 1;      // last 64-row k tile
    const int ri = lane & 7;
    const int tq = lane >> 3;
    const int r_lo = lane >> 2;
    const int cb = (lane & 3) * 2;

    // prefetch tiles 0, 1
    stage_tile(smb, b, 0, tid);            CP_COMMIT();
    stage_tile(smb + STAGE_B, b, 1, tid);  CP_COMMIT();

    // --- Q fragments: direct per-lane LDG from g_q, scale + split ---
    uint32_t qhi[4][4], qlo[4][4];
    {
        const float* qp = g_q + ((size_t)b * Tn + qbg + r_lo) * Hn;
#pragma unroll
        for (int k16 = 0; k16 < 4; ++k16) {
            int c0 = k16 * 16 + cb;
            float2 a00 = *(const float2*)(qp + c0);
            float2 a10 = *(const float2*)(qp + 8 * Hn + c0);
            float2 a01 = *(const float2*)(qp + c0 + 8);
            float2 a11 = *(const float2*)(qp + 8 * Hn + c0 + 8);
            a00.x *= 0.125f; a00.y *= 0.125f; a10.x *= 0.125f; a10.y *= 0.125f;
            a01.x *= 0.125f; a01.y *= 0.125f; a11.x *= 0.125f; a11.y *= 0.125f;
            qhi[k16][0] = pack_bf16(a00.x, a00.y);
            qhi[k16][1] = pack_bf16(a10.x, a10.y);
            qhi[k16][2] = pack_bf16(a01.x, a01.y);
            qhi[k16][3] = pack_bf16(a11.x, a11.y);
            qlo[k16][0] = pack_bf16(a00.x - bf16_hi_part(a00.x), a00.y - bf16_hi_part(a00.y));
            qlo[k16][1] = pack_bf16(a10.x - bf16_hi_part(a10.x), a10.y - bf16_hi_part(a10.y));
            qlo[k16][2] = pack_bf16(a01.x - bf16_hi_part(a01.x), a01.y - bf16_hi_part(a01.y));
            qlo[k16][3] = pack_bf16(a11.x - bf16_hi_part(a11.x), a11.y - bf16_hi_part(a11.y));
        }
    }

    float o[8][4];
#pragma unroll
    for (int nt = 0; nt < 8; ++nt)
#pragma unroll
        for (int e = 0; e < 4; ++e) o[nt][e] = 0.f;
    float m0 = -1e30f, m1 = -1e30f, l0 = 0.f, l1 = 0.f;

    for (int kt = 0; kt <= kmax; ++kt) {
        CP_WAIT(1);
        __syncthreads();    // tile kt visible to all warps

        const uint32_t stb = smb + (kt & 1) * STAGE_B;
        const bool active = (kt * 64) <= (qbg + 15);

        if (active) {
            // --- S = Q K^T ---
            float s[8][4];
#pragma unroll
            for (int nt = 0; nt < 8; ++nt)
#pragma unroll
                for (int e = 0; e < 4; ++e) s[nt][e] = 0.f;

#pragma unroll
            for (int k16 = 0; k16 < 4; ++k16) {
#pragma unroll
                for (int np = 0; np < 4; ++np) {
                    int krow = np * 16 + (tq >> 1) * 8 + ri;
                    int h = k16 * 16 + (tq & 1) * 8;
                    uint32_t kh[4], kl[4];
                    ldmatrix_x4(kh, stb + 0 * ARR_B + krow * 144 + h * 2);
                    ldmatrix_x4(kl, stb + 1 * ARR_B + krow * 144 + h * 2);
                    mma_bf16(s[2 * np],     qhi[k16], kh[0], kh[1]);
                    mma_bf16(s[2 * np],     qhi[k16], kl[0], kl[1]);
                    mma_bf16(s[2 * np],     qlo[k16], kh[0], kh[1]);
                    mma_bf16(s[2 * np + 1], qhi[k16], kh[2], kh[3]);
                    mma_bf16(s[2 * np + 1], qhi[k16], kl[2], kl[3]);
                    mma_bf16(s[2 * np + 1], qlo[k16], kh[2], kh[3]);
                }
            }

            // --- causal mask when tile crosses this warp's rows ---
            if (kt * 64 + 63 > qbg) {
                int r0 = qbg + r_lo, r1 = r0 + 8;
#pragma unroll
                for (int nt = 0; nt < 8; ++nt) {
                    int kc = kt * 64 + nt * 8 + cb;
                    if (kc > r0)     s[nt][0] = -1e30f;
                    if (kc + 1 > r0) s[nt][1] = -1e30f;
                    if (kc > r1)     s[nt][2] = -1e30f;
                    if (kc + 1 > r1) s[nt][3] = -1e30f;
                }
            }

            // --- online softmax (register-resident) ---
            float mx0 = -1e30f, mx1 = -1e30f;
#pragma unroll
            for (int nt = 0; nt < 8; ++nt) {
                mx0 = fmaxf(mx0, fmaxf(s[nt][0], s[nt][1]));
                mx1 = fmaxf(mx1, fmaxf(s[nt][2], s[nt][3]));
            }
            mx0 = fmaxf(mx0, __shfl_xor_sync(0xffffffffu, mx0, 1));
            mx0 = fmaxf(mx0, __shfl_xor_sync(0xffffffffu, mx0, 2));
            mx1 = fmaxf(mx1, __shfl_xor_sync(0xffffffffu, mx1, 1));
            mx1 = fmaxf(mx1, __shfl_xor_sync(0xffffffffu, mx1, 2));
            float mn0 = fmaxf(m0, mx0), mn1 = fmaxf(m1, mx1);
            float fac0 = __expf(m0 - mn0), fac1 = __expf(m1 - mn1);
            m0 = mn0; m1 = mn1;

            float sum0 = 0.f, sum1 = 0.f;
#pragma unroll
            for (int nt = 0; nt < 8; ++nt) {
                s[nt][0] = __expf(s[nt][0] - mn0);
                s[nt][1] = __expf(s[nt][1] - mn0);
                s[nt][2] = __expf(s[nt][2] - mn1);
                s[nt][3] = __expf(s[nt][3] - mn1);
                sum0 += s[nt][0] + s[nt][1];
                sum1 += s[nt][2] + s[nt][3];
            }
            sum0 += __shfl_xor_sync(0xffffffffu, sum0, 1);
            sum0 += __shfl_xor_sync(0xffffffffu, sum0, 2);
            sum1 += __shfl_xor_sync(0xffffffffu, sum1, 1);
            sum1 += __shfl_xor_sync(0xffffffffu, sum1, 2);
            l0 = l0 * fac0 + sum0;
            l1 = l1 * fac1 + sum1;

#pragma unroll
            for (int nt = 0; nt < 8; ++nt) {
                o[nt][0] *= fac0; o[nt][1] *= fac0;
                o[nt][2] *= fac1; o[nt][3] *= fac1;
            }

            // --- O += P V ---
#pragma unroll
            for (int kv = 0; kv < 4; ++kv) {
                uint32_t pa_hi[4], pa_lo[4];
                {
                    float p00 = s[2 * kv][0],     p01 = s[2 * kv][1];
                    float p02 = s[2 * kv][2],     p03 = s[2 * kv][3];
                    float p10 = s[2 * kv + 1][0], p11 = s[2 * kv + 1][1];
                    float p12 = s[2 * kv + 1][2], p13 = s[2 * kv + 1][3];
                    pa_hi[0] = pack_bf16(p00, p01);
                    pa_hi[1] = pack_bf16(p02, p03);
                    pa_hi[2] = pack_bf16(p10, p11);
                    pa_hi[3] = pack_bf16(p12, p13);
                    pa_lo[0] = pack_bf16(p00 - bf16_hi_part(p00), p01 - bf16_hi_part(p01));
                    pa_lo[1] = pack_bf16(p02 - bf16_hi_part(p02), p03 - bf16_hi_part(p03));
                    pa_lo[2] = pack_bf16(p10 - bf16_hi_part(p10), p11 - bf16_hi_part(p11));
                    pa_lo[3] = pack_bf16(p12 - bf16_hi_part(p12), p13 - bf16_hi_part(p13));
                }
#pragma unroll
                for (int np = 0; np < 4; ++np) {
                    int krow = kv * 16 + (tq & 1) * 8 + ri;
                    int h = np * 16 + (tq >> 1) * 8;
                    uint32_t vh[4], vl[4];
                    ldmatrix_x4_trans(vh, stb + 2 * ARR_B + krow * 144 + h * 2);
                    ldmatrix_x4_trans(vl, stb + 3 * ARR_B + krow * 144 + h * 2);
                    mma_bf16(o[2 * np],     pa_hi, vh[0], vh[1]);
                    mma_bf16(o[2 * np],     pa_hi, vl[0], vl[1]);
                    mma_bf16(o[2 * np],     pa_lo, vh[0], vh[1]);
                    mma_bf16(o[2 * np + 1], pa_hi, vh[2], vh[3]);
                    mma_bf16(o[2 * np + 1], pa_hi, vl[2], vl[3]);
                    mma_bf16(o[2 * np + 1], pa_lo, vh[2], vh[3]);
                }
            }
        }

        __syncthreads();    // all warps done reading stage (kt&1)
        if (kt + 2 <= kmax) {
            stage_tile(smb + (kt & 1) * STAGE_B, b, kt + 2, tid);
            CP_COMMIT();
        } else {
            CP_COMMIT();    // empty group keeps wait_group counting uniform
        }
    }

    // --- normalize + store ---
    float inv0 = 1.0f / l0, inv1 = 1.0f / l1;
    size_t gr0 = ((size_t)b * Tn + qbg + r_lo) * Hn;
    size_t gr1 = gr0 + 8 * Hn;
#pragma unroll
    for (int nt = 0; nt < 8; ++nt) {
        int col = nt * 8 + cb;
        *(float2*)&out[gr0 + col] = make_float2(o[nt][0] * inv0, o[nt][1] * inv0);
        *(float2*)&out[gr1 + col] = make_float2(o[nt][2] * inv1, o[nt][3] * inv1);
    }
}

// ---------------------------------------------------------------------------
extern "C" void kernel_launch(void* const* d_in, const int* in_sizes, int n_in,
                              void* d_out, int out_size)
{
    const float* x  = (const float*)d_in[0];
    const float* Wk = (const float*)d_in[1];
    const float* Wq = (const float*)d_in[2];
    const float* Wv = (const float*)d_in[3];
    float* out = (float*)d_out;

    prep_w_kernel<<<(24 * 24 * 32 + 255) / 256, 256>>>(Wk, Wq, Wv);

    cudaFuncSetAttribute(proj_mma_kernel,
                         cudaFuncAttributeMaxDynamicSharedMemorySize, PROJ_SMEM);
    proj_mma_kernel<<<(Bn * Tn) / 128, 256, PROJ_SMEM>>>(x);

    cudaFuncSetAttribute(attn_mma_kernel,
                         cudaFuncAttributeMaxDynamicSharedMemorySize, ATTN_SMEM);
    attn_mma_kernel<<<dim3(Tn / 128, Bn), 256, ATTN_SMEM>>>(out);
}

// round 8
// speedup vs baseline: 2.7033x; 1.1654x over previous
#include <cuda_runtime.h>
#include <cuda_bf16.h>
#include <cuda_fp16.h>
#include <cstdint>

#define Bn 1024
#define Tn 256
#define Cn 384
#define Hn 64

__device__ float g_q[Bn * Tn * Hn];
// K/V pre-split bf16 hi/lo, packed 2 cols per uint32: idx = row*32 + col/2
__device__ __align__(16) uint32_t g_khi[Bn * Tn * 32];
__device__ __align__(16) uint32_t g_klo[Bn * Tn * 32];
__device__ __align__(16) uint32_t g_vhi[Bn * Tn * 32];
__device__ __align__(16) uint32_t g_vlo[Bn * Tn * 32];

// Pre-packed fp16 B fragments (Whi only) for mma.sync.m16n8k16 (row.col):
// index ((kt*24 + nt)*32 + lane) -> {bhi_r0, bhi_r1}
__device__ __align__(16) uint2 g_bfrag[24 * 24 * 32];

// ---------------------------------------------------------------------------
__device__ __forceinline__ uint32_t smem_u32(const void* p) {
    uint32_t a;
    asm("{ .reg .u64 t; cvta.to.shared.u64 t, %1; cvt.u32.u64 %0, t; }" : "=r"(a) : "l"(p));
    return a;
}
__device__ __forceinline__ uint32_t pack_bf16(float a, float b) {
    uint32_t lo = __bfloat16_as_ushort(__float2bfloat16_rn(a));
    uint32_t hi = __bfloat16_as_ushort(__float2bfloat16_rn(b));
    return lo | (hi << 16);
}
__device__ __forceinline__ float bf16_hi_part(float v) {
    return __bfloat162float(__float2bfloat16_rn(v));
}
__device__ __forceinline__ uint32_t pack_fp16(float a, float b) {
    uint32_t lo = __half_as_ushort(__float2half_rn(a));
    uint32_t hi = __half_as_ushort(__float2half_rn(b));
    return lo | (hi << 16);
}
__device__ __forceinline__ float fp16_hi_part(float v) {
    return __half2float(__float2half_rn(v));
}
__device__ __forceinline__ void mma_bf16(float* c, const uint32_t* a,
                                         uint32_t b0, uint32_t b1) {
    asm volatile(
        "mma.sync.aligned.m16n8k16.row.col.f32.bf16.bf16.f32 "
        "{%0,%1,%2,%3}, {%4,%5,%6,%7}, {%8,%9}, {%0,%1,%2,%3};"
        : "+f"(c[0]), "+f"(c[1]), "+f"(c[2]), "+f"(c[3])
        : "r"(a[0]), "r"(a[1]), "r"(a[2]), "r"(a[3]), "r"(b0), "r"(b1));
}
__device__ __forceinline__ void mma_fp16(float* c, const uint32_t* a,
                                         uint32_t b0, uint32_t b1) {
    asm volatile(
        "mma.sync.aligned.m16n8k16.row.col.f32.f16.f16.f32 "
        "{%0,%1,%2,%3}, {%4,%5,%6,%7}, {%8,%9}, {%0,%1,%2,%3};"
        : "+f"(c[0]), "+f"(c[1]), "+f"(c[2]), "+f"(c[3])
        : "r"(a[0]), "r"(a[1]), "r"(a[2]), "r"(a[3]), "r"(b0), "r"(b1));
}
__device__ __forceinline__ void ldmatrix_x4(uint32_t* r, uint32_t addr) {
    asm volatile(
        "ldmatrix.sync.aligned.m8n8.x4.shared.b16 {%0,%1,%2,%3}, [%4];"
        : "=r"(r[0]), "=r"(r[1]), "=r"(r[2]), "=r"(r[3]) : "r"(addr));
}
__device__ __forceinline__ void ldmatrix_x4_trans(uint32_t* r, uint32_t addr) {
    asm volatile(
        "ldmatrix.sync.aligned.m8n8.x4.trans.shared.b16 {%0,%1,%2,%3}, [%4];"
        : "=r"(r[0]), "=r"(r[1]), "=r"(r[2]), "=r"(r[3]) : "r"(addr));
}
#define CP_ASYNC16(dst, src) \
    asm volatile("cp.async.cg.shared.global [%0], [%1], 16;" :: "r"(dst), "l"(src))
#define CP_COMMIT() asm volatile("cp.async.commit_group;" ::: "memory")
#define CP_WAIT(n)  asm volatile("cp.async.wait_group %0;" :: "n"(n) : "memory")

// ---------------------------------------------------------------------------
// Weight prep: fp16 Whi fragments in mma.sync register layout (hi only).
// ---------------------------------------------------------------------------
__global__ void prep_w_kernel(const float* __restrict__ Wk,
                              const float* __restrict__ Wq,
                              const float* __restrict__ Wv) {
    int idx = blockIdx.x * 256 + threadIdx.x;
    if (idx >= 24 * 24 * 32) return;
    int lane = idx & 31;
    int nt = (idx >> 5) % 24;
    int kt = (idx >> 5) / 24;

    int n = nt * 8 + (lane >> 2);
    int k0 = kt * 16 + (lane & 3) * 2;
    const float* W = (n < 64) ? Wq : (n < 128) ? Wk : Wv;
    int nc = n & 63;

    float w00 = W[(k0 + 0) * Hn + nc];
    float w01 = W[(k0 + 1) * Hn + nc];
    float w10 = W[(k0 + 8) * Hn + nc];
    float w11 = W[(k0 + 9) * Hn + nc];

    uint2 f;
    f.x = pack_fp16(w00, w01);
    f.y = pack_fp16(w10, w11);
    g_bfrag[idx] = f;
}

// ---------------------------------------------------------------------------
// Projection GEMM: 2-product fp16 split. A = xhi + xlo (fp16 split, exact),
// B = fp16(W). y = (xhi + xlo) * Whi  -> error == x * Wlo only (~1.7e-4 rel).
// Block tile M=128, N=192; 8 warps (4 x M, 2 x N). 12 k-chunks of 32.
// ---------------------------------------------------------------------------
#define SB_OFF_U8 40960
#define PROJ_SMEM (40960 + 2 * 12288)

__global__ __launch_bounds__(256) void proj_mma_kernel(const float* __restrict__ x) {
    extern __shared__ __align__(16) char psm[];
    uint32_t* sA = (uint32_t*)psm;                    // [(st*2+hilo)*2560 + idx]
    uint2*    sB = (uint2*)(psm + SB_OFF_U8);         // [st*1536 + frag]

    const int tid = threadIdx.x;
    const int wid = tid >> 5;
    const int lane = tid & 31;
    const int row0 = blockIdx.x * 128;

    const int wm = (wid & 3) * 32;
    const int nw = wid >> 2;

    const int xr = tid >> 1;
    const int xc = (tid & 1) * 16;
    const float* xrow = x + (size_t)(row0 + xr) * Cn + xc;
    const char* gB = (const char*)g_bfrag;

    // prologue: B chunk 0 (12288B = 768 x 16B) via cp.async
#pragma unroll
    for (int j = 0; j < 3; ++j)
        CP_ASYNC16(smem_u32((char*)sB + (tid + j * 256) * 16),
                   gB + (tid + j * 256) * 16);
    CP_COMMIT();

    float4 v[4];
#pragma unroll
    for (int j = 0; j < 4; ++j) v[j] = __ldg((const float4*)xrow + j);
    {
        const int base = xr * 20 + xc / 2;
#pragma unroll
        for (int j = 0; j < 4; ++j) {
            float hx = fp16_hi_part(v[j].x), hy = fp16_hi_part(v[j].y);
            float hz = fp16_hi_part(v[j].z), hw = fp16_hi_part(v[j].w);
            sA[base + 2 * j + 0]        = pack_fp16(hx, hy);
            sA[base + 2 * j + 1]        = pack_fp16(hz, hw);
            sA[2560 + base + 2 * j + 0] = pack_fp16(v[j].x - hx, v[j].y - hy);
            sA[2560 + base + 2 * j + 1] = pack_fp16(v[j].z - hz, v[j].w - hw);
        }
    }

    float acc[2][12][4];
#pragma unroll
    for (int mt = 0; mt < 2; ++mt)
#pragma unroll
        for (int nt = 0; nt < 12; ++nt)
#pragma unroll
            for (int e = 0; e < 4; ++e) acc[mt][nt][e] = 0.f;

    const int lrow = lane & 15;
    const int lk8 = (lane >> 4) * 8;

    for (int c = 0; c < 12; ++c) {
        const int st = c & 1;

        if (c < 11) {
#pragma unroll
            for (int j = 0; j < 3; ++j)
                CP_ASYNC16(smem_u32((char*)sB + (st ^ 1) * 12288 + (tid + j * 256) * 16),
                           gB + (c + 1) * 12288 + (tid + j * 256) * 16);
            CP_COMMIT();
            const float* nx = xrow + (c + 1) * 32;
#pragma unroll
            for (int j = 0; j < 4; ++j) v[j] = __ldg((const float4*)nx + j);
        }
        if (c < 11) { CP_WAIT(1); } else { CP_WAIT(0); }
        __syncthreads();   // B_c arrived + A_c stores visible + stage free

        const uint32_t aHiBase = smem_u32(&sA[(st * 2 + 0) * 2560]);
        const uint32_t aLoBase = smem_u32(&sA[(st * 2 + 1) * 2560]);

#pragma unroll
        for (int kt = 0; kt < 2; ++kt) {
            uint32_t ahi[2][4], alo[2][4];
#pragma unroll
            for (int mt = 0; mt < 2; ++mt) {
                uint32_t off = (uint32_t)((wm + mt * 16 + lrow) * 80 +
                                          (kt * 16 + lk8) * 2);
                ldmatrix_x4(ahi[mt], aHiBase + off);
                ldmatrix_x4(alo[mt], aLoBase + off);
            }
            const uint2* bp = sB + (st * 1536 + ((kt * 24 + nw * 12) * 32 + lane));
#pragma unroll
            for (int nt = 0; nt < 12; ++nt) {
                uint2 bf = bp[nt * 32];
#pragma unroll
                for (int mt = 0; mt < 2; ++mt) {
                    mma_fp16(acc[mt][nt], ahi[mt], bf.x, bf.y);   // xhi * Whi
                    mma_fp16(acc[mt][nt], alo[mt], bf.x, bf.y);   // xlo * Whi
                }
            }
        }

        if (c < 11) {
            __syncthreads();   // all warps done with mma(c) -> sA[st^1] free
            const int base = (st ^ 1) * 2 * 2560 + xr * 20 + xc / 2;
#pragma unroll
            for (int j = 0; j < 4; ++j) {
                float hx = fp16_hi_part(v[j].x), hy = fp16_hi_part(v[j].y);
                float hz = fp16_hi_part(v[j].z), hw = fp16_hi_part(v[j].w);
                sA[base + 2 * j + 0]        = pack_fp16(hx, hy);
                sA[base + 2 * j + 1]        = pack_fp16(hz, hw);
                sA[2560 + base + 2 * j + 0] = pack_fp16(v[j].x - hx, v[j].y - hy);
                sA[2560 + base + 2 * j + 1] = pack_fp16(v[j].z - hz, v[j].w - hw);
            }
        }
    }

    // --- Epilogue: Q fp32; K/V pre-split bf16 hi/lo packed pairs ---
#pragma unroll
    for (int mt = 0; mt < 2; ++mt) {
#pragma unroll
        for (int nt = 0; nt < 12; ++nt) {
            int n = nw * 96 + nt * 8 + (lane & 3) * 2;
            size_t r0g = (size_t)(row0 + wm + mt * 16 + (lane >> 2));
            float v0 = acc[mt][nt][0], v1 = acc[mt][nt][1];
            float v2 = acc[mt][nt][2], v3 = acc[mt][nt][3];
            if (n < 64) {
                *(float2*)&g_q[r0g * Hn + n]       = make_float2(v0, v1);
                *(float2*)&g_q[(r0g + 8) * Hn + n] = make_float2(v2, v3);
            } else {
                uint32_t* hi = (n < 128) ? g_khi : g_vhi;
                uint32_t* lo = (n < 128) ? g_klo : g_vlo;
                int col2 = (n & 63) >> 1;
                float h0 = bf16_hi_part(v0), h1 = bf16_hi_part(v1);
                float h2 = bf16_hi_part(v2), h3 = bf16_hi_part(v3);
                hi[r0g * 32 + col2]       = pack_bf16(v0, v1);
                lo[r0g * 32 + col2]       = pack_bf16(v0 - h0, v1 - h1);
                hi[(r0g + 8) * 32 + col2] = pack_bf16(v2, v3);
                lo[(r0g + 8) * 32 + col2] = pack_bf16(v2 - h2, v3 - h3);
            }
        }
    }
}

// ---------------------------------------------------------------------------
// Flash-attention: unchanged from R7 (passing, bf16 3-product).
// ---------------------------------------------------------------------------
#define ARR_B   9216
#define STAGE_B (4 * ARR_B)
#define ATTN_SMEM (2 * STAGE_B)

__device__ __forceinline__ void stage_tile(uint32_t dst, int b, int kt, int tid) {
    size_t base_byte = (((size_t)b * Tn + kt * 64) * 64) * 2;
    const char* pkh = (const char*)g_khi + base_byte;
    const char* pkl = (const char*)g_klo + base_byte;
    const char* pvh = (const char*)g_vhi + base_byte;
    const char* pvl = (const char*)g_vlo + base_byte;
#pragma unroll
    for (int i = 0; i < 2; ++i) {
        int g = tid * 2 + i;
        uint32_t doff = (uint32_t)((g >> 3) * 144 + (g & 7) * 16);
        CP_ASYNC16(dst + 0 * ARR_B + doff, pkh + g * 16);
        CP_ASYNC16(dst + 1 * ARR_B + doff, pkl + g * 16);
        CP_ASYNC16(dst + 2 * ARR_B + doff, pvh + g * 16);
        CP_ASYNC16(dst + 3 * ARR_B + doff, pvl + g * 16);
    }
}

__global__ __launch_bounds__(256) void attn_mma_kernel(float* __restrict__ out)
{
    extern __shared__ __align__(16) char tsm[];
    const uint32_t smb = smem_u32(tsm);

    const int tid = threadIdx.x;
    const int wid = tid >> 5;
    const int lane = tid & 31;
    const int qt = blockIdx.x;        // 0..1 (128-row q tiles)
    const int b = blockIdx.y;
    const int qb = wid * 16;
    const int qbg = qt * 128 + qb;
    const int kmax = qt * 2 + 1;
    const int ri = lane & 7;
    const int tq = lane >> 3;
    const int r_lo = lane >> 2;
    const int cb = (lane & 3) * 2;

    stage_tile(smb, b, 0, tid);            CP_COMMIT();
    stage_tile(smb + STAGE_B, b, 1, tid);  CP_COMMIT();

    uint32_t qhi[4][4], qlo[4][4];
    {
        const float* qp = g_q + ((size_t)b * Tn + qbg + r_lo) * Hn;
#pragma unroll
        for (int k16 = 0; k16 < 4; ++k16) {
            int c0 = k16 * 16 + cb;
            float2 a00 = *(const float2*)(qp + c0);
            float2 a10 = *(const float2*)(qp + 8 * Hn + c0);
            float2 a01 = *(const float2*)(qp + c0 + 8);
            float2 a11 = *(const float2*)(qp + 8 * Hn + c0 + 8);
            a00.x *= 0.125f; a00.y *= 0.125f; a10.x *= 0.125f; a10.y *= 0.125f;
            a01.x *= 0.125f; a01.y *= 0.125f; a11.x *= 0.125f; a11.y *= 0.125f;
            qhi[k16][0] = pack_bf16(a00.x, a00.y);
            qhi[k16][1] = pack_bf16(a10.x, a10.y);
            qhi[k16][2] = pack_bf16(a01.x, a01.y);
            qhi[k16][3] = pack_bf16(a11.x, a11.y);
            qlo[k16][0] = pack_bf16(a00.x - bf16_hi_part(a00.x), a00.y - bf16_hi_part(a00.y));
            qlo[k16][1] = pack_bf16(a10.x - bf16_hi_part(a10.x), a10.y - bf16_hi_part(a10.y));
            qlo[k16][2] = pack_bf16(a01.x - bf16_hi_part(a01.x), a01.y - bf16_hi_part(a01.y));
            qlo[k16][3] = pack_bf16(a11.x - bf16_hi_part(a11.x), a11.y - bf16_hi_part(a11.y));
        }
    }

    float o[8][4];
#pragma unroll
    for (int nt = 0; nt < 8; ++nt)
#pragma unroll
        for (int e = 0; e < 4; ++e) o[nt][e] = 0.f;
    float m0 = -1e30f, m1 = -1e30f, l0 = 0.f, l1 = 0.f;

    for (int kt = 0; kt <= kmax; ++kt) {
        CP_WAIT(1);
        __syncthreads();

        const uint32_t stb = smb + (kt & 1) * STAGE_B;
        const bool active = (kt * 64) <= (qbg + 15);

        if (active) {
            float s[8][4];
#pragma unroll
            for (int nt = 0; nt < 8; ++nt)
#pragma unroll
                for (int e = 0; e < 4; ++e) s[nt][e] = 0.f;

#pragma unroll
            for (int k16 = 0; k16 < 4; ++k16) {
#pragma unroll
                for (int np = 0; np < 4; ++np) {
                    int krow = np * 16 + (tq >> 1) * 8 + ri;
                    int h = k16 * 16 + (tq & 1) * 8;
                    uint32_t kh[4], kl[4];
                    ldmatrix_x4(kh, stb + 0 * ARR_B + krow * 144 + h * 2);
                    ldmatrix_x4(kl, stb + 1 * ARR_B + krow * 144 + h * 2);
                    mma_bf16(s[2 * np],     qhi[k16], kh[0], kh[1]);
                    mma_bf16(s[2 * np],     qhi[k16], kl[0], kl[1]);
                    mma_bf16(s[2 * np],     qlo[k16], kh[0], kh[1]);
                    mma_bf16(s[2 * np + 1], qhi[k16], kh[2], kh[3]);
                    mma_bf16(s[2 * np + 1], qhi[k16], kl[2], kl[3]);
                    mma_bf16(s[2 * np + 1], qlo[k16], kh[2], kh[3]);
                }
            }

            if (kt * 64 + 63 > qbg) {
                int r0 = qbg + r_lo, r1 = r0 + 8;
#pragma unroll
                for (int nt = 0; nt < 8; ++nt) {
                    int kc = kt * 64 + nt * 8 + cb;
                    if (kc > r0)     s[nt][0] = -1e30f;
                    if (kc + 1 > r0) s[nt][1] = -1e30f;
                    if (kc > r1)     s[nt][2] = -1e30f;
                    if (kc + 1 > r1) s[nt][3] = -1e30f;
                }
            }

            float mx0 = -1e30f, mx1 = -1e30f;
#pragma unroll
            for (int nt = 0; nt < 8; ++nt) {
                mx0 = fmaxf(mx0, fmaxf(s[nt][0], s[nt][1]));
                mx1 = fmaxf(mx1, fmaxf(s[nt][2], s[nt][3]));
            }
            mx0 = fmaxf(mx0, __shfl_xor_sync(0xffffffffu, mx0, 1));
            mx0 = fmaxf(mx0, __shfl_xor_sync(0xffffffffu, mx0, 2));
            mx1 = fmaxf(mx1, __shfl_xor_sync(0xffffffffu, mx1, 1));
            mx1 = fmaxf(mx1, __shfl_xor_sync(0xffffffffu, mx1, 2));
            float mn0 = fmaxf(m0, mx0), mn1 = fmaxf(m1, mx1);
            float fac0 = __expf(m0 - mn0), fac1 = __expf(m1 - mn1);
            m0 = mn0; m1 = mn1;

            float sum0 = 0.f, sum1 = 0.f;
#pragma unroll
            for (int nt = 0; nt < 8; ++nt) {
                s[nt][0] = __expf(s[nt][0] - mn0);
                s[nt][1] = __expf(s[nt][1] - mn0);
                s[nt][2] = __expf(s[nt][2] - mn1);
                s[nt][3] = __expf(s[nt][3] - mn1);
                sum0 += s[nt][0] + s[nt][1];
                sum1 += s[nt][2] + s[nt][3];
            }
            sum0 += __shfl_xor_sync(0xffffffffu, sum0, 1);
            sum0 += __shfl_xor_sync(0xffffffffu, sum0, 2);
            sum1 += __shfl_xor_sync(0xffffffffu, sum1, 1);
            sum1 += __shfl_xor_sync(0xffffffffu, sum1, 2);
            l0 = l0 * fac0 + sum0;
            l1 = l1 * fac1 + sum1;

#pragma unroll
            for (int nt = 0; nt < 8; ++nt) {
                o[nt][0] *= fac0; o[nt][1] *= fac0;
                o[nt][2] *= fac1; o[nt][3] *= fac1;
            }

#pragma unroll
            for (int kv = 0; kv < 4; ++kv) {
                uint32_t pa_hi[4], pa_lo[4];
                {
                    float p00 = s[2 * kv][0],     p01 = s[2 * kv][1];
                    float p02 = s[2 * kv][2],     p03 = s[2 * kv][3];
                    float p10 = s[2 * kv + 1][0], p11 = s[2 * kv + 1][1];
                    float p12 = s[2 * kv + 1][2], p13 = s[2 * kv + 1][3];
                    pa_hi[0] = pack_bf16(p00, p01);
                    pa_hi[1] = pack_bf16(p02, p03);
                    pa_hi[2] = pack_bf16(p10, p11);
                    pa_hi[3] = pack_bf16(p12, p13);
                    pa_lo[0] = pack_bf16(p00 - bf16_hi_part(p00), p01 - bf16_hi_part(p01));
                    pa_lo[1] = pack_bf16(p02 - bf16_hi_part(p02), p03 - bf16_hi_part(p03));
                    pa_lo[2] = pack_bf16(p10 - bf16_hi_part(p10), p11 - bf16_hi_part(p11));
                    pa_lo[3] = pack_bf16(p12 - bf16_hi_part(p12), p13 - bf16_hi_part(p13));
                }
#pragma unroll
                for (int np = 0; np < 4; ++np) {
                    int krow = kv * 16 + (tq & 1) * 8 + ri;
                    int h = np * 16 + (tq >> 1) * 8;
                    uint32_t vh[4], vl[4];
                    ldmatrix_x4_trans(vh, stb + 2 * ARR_B + krow * 144 + h * 2);
                    ldmatrix_x4_trans(vl, stb + 3 * ARR_B + krow * 144 + h * 2);
                    mma_bf16(o[2 * np],     pa_hi, vh[0], vh[1]);
                    mma_bf16(o[2 * np],     pa_hi, vl[0], vl[1]);
                    mma_bf16(o[2 * np],     pa_lo, vh[0], vh[1]);
                    mma_bf16(o[2 * np + 1], pa_hi, vh[2], vh[3]);
                    mma_bf16(o[2 * np + 1], pa_hi, vl[2], vl[3]);
                    mma_bf16(o[2 * np + 1], pa_lo, vh[2], vh[3]);
                }
            }
        }

        __syncthreads();
        if (kt + 2 <= kmax) {
            stage_tile(smb + (kt & 1) * STAGE_B, b, kt + 2, tid);
            CP_COMMIT();
        } else {
            CP_COMMIT();
        }
    }

    float inv0 = 1.0f / l0, inv1 = 1.0f / l1;
    size_t gr0 = ((size_t)b * Tn + qbg + r_lo) * Hn;
    size_t gr1 = gr0 + 8 * Hn;
#pragma unroll
    for (int nt = 0; nt < 8; ++nt) {
        int col = nt * 8 + cb;
        *(float2*)&out[gr0 + col] = make_float2(o[nt][0] * inv0, o[nt][1] * inv0);
        *(float2*)&out[gr1 + col] = make_float2(o[nt][2] * inv1, o[nt][3] * inv1);
    }
}

// ---------------------------------------------------------------------------
extern "C" void kernel_launch(void* const* d_in, const int* in_sizes, int n_in,
                              void* d_out, int out_size)
{
    const float* x  = (const float*)d_in[0];
    const float* Wk = (const float*)d_in[1];
    const float* Wq = (const float*)d_in[2];
    const float* Wv = (const float*)d_in[3];
    float* out = (float*)d_out;

    prep_w_kernel<<<(24 * 24 * 32 + 255) / 256, 256>>>(Wk, Wq, Wv);

    cudaFuncSetAttribute(proj_mma_kernel,
                         cudaFuncAttributeMaxDynamicSharedMemorySize, PROJ_SMEM);
    proj_mma_kernel<<<(Bn * Tn) / 128, 256, PROJ_SMEM>>>(x);

    cudaFuncSetAttribute(attn_mma_kernel,
                         cudaFuncAttributeMaxDynamicSharedMemorySize, ATTN_SMEM);
    attn_mma_kernel<<<dim3(Tn / 128, Bn), 256, ATTN_SMEM>>>(out);
}

// round 9
// speedup vs baseline: 2.9939x; 1.1075x over previous
#include <cuda_runtime.h>
#include <cuda_bf16.h>
#include <cuda_fp16.h>
#include <cstdint>

#define Bn 1024
#define Tn 256
#define Cn 384
#define Hn 64

__device__ float g_q[Bn * Tn * Hn];
// K/V as fp16, packed 2 cols per uint32: idx = row*32 + col/2
__device__ __align__(16) uint32_t g_k16[Bn * Tn * 32];
__device__ __align__(16) uint32_t g_v16[Bn * Tn * 32];

// Pre-packed fp16 B fragments (Whi only) for mma.sync.m16n8k16 (row.col)
__device__ __align__(16) uint2 g_bfrag[24 * 24 * 32];

// ---------------------------------------------------------------------------
__device__ __forceinline__ uint32_t smem_u32(const void* p) {
    uint32_t a;
    asm("{ .reg .u64 t; cvta.to.shared.u64 t, %1; cvt.u32.u64 %0, t; }" : "=r"(a) : "l"(p));
    return a;
}
__device__ __forceinline__ uint32_t pack_fp16(float a, float b) {
    uint32_t lo = __half_as_ushort(__float2half_rn(a));
    uint32_t hi = __half_as_ushort(__float2half_rn(b));
    return lo | (hi << 16);
}
__device__ __forceinline__ float fp16_hi_part(float v) {
    return __half2float(__float2half_rn(v));
}
__device__ __forceinline__ void mma_fp16(float* c, const uint32_t* a,
                                         uint32_t b0, uint32_t b1) {
    asm volatile(
        "mma.sync.aligned.m16n8k16.row.col.f32.f16.f16.f32 "
        "{%0,%1,%2,%3}, {%4,%5,%6,%7}, {%8,%9}, {%0,%1,%2,%3};"
        : "+f"(c[0]), "+f"(c[1]), "+f"(c[2]), "+f"(c[3])
        : "r"(a[0]), "r"(a[1]), "r"(a[2]), "r"(a[3]), "r"(b0), "r"(b1));
}
__device__ __forceinline__ void ldmatrix_x4(uint32_t* r, uint32_t addr) {
    asm volatile(
        "ldmatrix.sync.aligned.m8n8.x4.shared.b16 {%0,%1,%2,%3}, [%4];"
        : "=r"(r[0]), "=r"(r[1]), "=r"(r[2]), "=r"(r[3]) : "r"(addr));
}
__device__ __forceinline__ void ldmatrix_x4_trans(uint32_t* r, uint32_t addr) {
    asm volatile(
        "ldmatrix.sync.aligned.m8n8.x4.trans.shared.b16 {%0,%1,%2,%3}, [%4];"
        : "=r"(r[0]), "=r"(r[1]), "=r"(r[2]), "=r"(r[3]) : "r"(addr));
}
#define CP_ASYNC16(dst, src) \
    asm volatile("cp.async.cg.shared.global [%0], [%1], 16;" :: "r"(dst), "l"(src))
#define CP_COMMIT() asm volatile("cp.async.commit_group;" ::: "memory")
#define CP_WAIT(n)  asm volatile("cp.async.wait_group %0;" :: "n"(n) : "memory")

// ---------------------------------------------------------------------------
// Weight prep: fp16 Whi fragments in mma.sync register layout (hi only).
// ---------------------------------------------------------------------------
__global__ void prep_w_kernel(const float* __restrict__ Wk,
                              const float* __restrict__ Wq,
                              const float* __restrict__ Wv) {
    int idx = blockIdx.x * 256 + threadIdx.x;
    if (idx >= 24 * 24 * 32) return;
    int lane = idx & 31;
    int nt = (idx >> 5) % 24;
    int kt = (idx >> 5) / 24;

    int n = nt * 8 + (lane >> 2);
    int k0 = kt * 16 + (lane & 3) * 2;
    const float* W = (n < 64) ? Wq : (n < 128) ? Wk : Wv;
    int nc = n & 63;

    uint2 f;
    f.x = pack_fp16(W[(k0 + 0) * Hn + nc], W[(k0 + 1) * Hn + nc]);
    f.y = pack_fp16(W[(k0 + 8) * Hn + nc], W[(k0 + 9) * Hn + nc]);
    g_bfrag[idx] = f;
}

// ---------------------------------------------------------------------------
// Projection GEMM: 2-product fp16 split (identical mainloop to R8).
// ---------------------------------------------------------------------------
#define SB_OFF_U8 40960
#define PROJ_SMEM (40960 + 2 * 12288)

__global__ __launch_bounds__(256) void proj_mma_kernel(const float* __restrict__ x) {
    extern __shared__ __align__(16) char psm[];
    uint32_t* sA = (uint32_t*)psm;
    uint2*    sB = (uint2*)(psm + SB_OFF_U8);

    const int tid = threadIdx.x;
    const int wid = tid >> 5;
    const int lane = tid & 31;
    const int row0 = blockIdx.x * 128;

    const int wm = (wid & 3) * 32;
    const int nw = wid >> 2;

    const int xr = tid >> 1;
    const int xc = (tid & 1) * 16;
    const float* xrow = x + (size_t)(row0 + xr) * Cn + xc;
    const char* gB = (const char*)g_bfrag;

#pragma unroll
    for (int j = 0; j < 3; ++j)
        CP_ASYNC16(smem_u32((char*)sB + (tid + j * 256) * 16),
                   gB + (tid + j * 256) * 16);
    CP_COMMIT();

    float4 v[4];
#pragma unroll
    for (int j = 0; j < 4; ++j) v[j] = __ldg((const float4*)xrow + j);
    {
        const int base = xr * 20 + xc / 2;
#pragma unroll
        for (int j = 0; j < 4; ++j) {
            float hx = fp16_hi_part(v[j].x), hy = fp16_hi_part(v[j].y);
            float hz = fp16_hi_part(v[j].z), hw = fp16_hi_part(v[j].w);
            sA[base + 2 * j + 0]        = pack_fp16(hx, hy);
            sA[base + 2 * j + 1]        = pack_fp16(hz, hw);
            sA[2560 + base + 2 * j + 0] = pack_fp16(v[j].x - hx, v[j].y - hy);
            sA[2560 + base + 2 * j + 1] = pack_fp16(v[j].z - hz, v[j].w - hw);
        }
    }

    float acc[2][12][4];
#pragma unroll
    for (int mt = 0; mt < 2; ++mt)
#pragma unroll
        for (int nt = 0; nt < 12; ++nt)
#pragma unroll
            for (int e = 0; e < 4; ++e) acc[mt][nt][e] = 0.f;

    const int lrow = lane & 15;
    const int lk8 = (lane >> 4) * 8;

    for (int c = 0; c < 12; ++c) {
        const int st = c & 1;

        if (c < 11) {
#pragma unroll
            for (int j = 0; j < 3; ++j)
                CP_ASYNC16(smem_u32((char*)sB + (st ^ 1) * 12288 + (tid + j * 256) * 16),
                           gB + (c + 1) * 12288 + (tid + j * 256) * 16);
            CP_COMMIT();
            const float* nx = xrow + (c + 1) * 32;
#pragma unroll
            for (int j = 0; j < 4; ++j) v[j] = __ldg((const float4*)nx + j);
        }
        if (c < 11) { CP_WAIT(1); } else { CP_WAIT(0); }
        __syncthreads();

        const uint32_t aHiBase = smem_u32(&sA[(st * 2 + 0) * 2560]);
        const uint32_t aLoBase = smem_u32(&sA[(st * 2 + 1) * 2560]);

#pragma unroll
        for (int kt = 0; kt < 2; ++kt) {
            uint32_t ahi[2][4], alo[2][4];
#pragma unroll
            for (int mt = 0; mt < 2; ++mt) {
                uint32_t off = (uint32_t)((wm + mt * 16 + lrow) * 80 +
                                          (kt * 16 + lk8) * 2);
                ldmatrix_x4(ahi[mt], aHiBase + off);
                ldmatrix_x4(alo[mt], aLoBase + off);
            }
            const uint2* bp = sB + (st * 1536 + ((kt * 24 + nw * 12) * 32 + lane));
#pragma unroll
            for (int nt = 0; nt < 12; ++nt) {
                uint2 bf = bp[nt * 32];
#pragma unroll
                for (int mt = 0; mt < 2; ++mt) {
                    mma_fp16(acc[mt][nt], ahi[mt], bf.x, bf.y);
                    mma_fp16(acc[mt][nt], alo[mt], bf.x, bf.y);
                }
            }
        }

        if (c < 11) {
            __syncthreads();
            const int base = (st ^ 1) * 2 * 2560 + xr * 20 + xc / 2;
#pragma unroll
            for (int j = 0; j < 4; ++j) {
                float hx = fp16_hi_part(v[j].x), hy = fp16_hi_part(v[j].y);
                float hz = fp16_hi_part(v[j].z), hw = fp16_hi_part(v[j].w);
                sA[base + 2 * j + 0]        = pack_fp16(hx, hy);
                sA[base + 2 * j + 1]        = pack_fp16(hz, hw);
                sA[2560 + base + 2 * j + 0] = pack_fp16(v[j].x - hx, v[j].y - hy);
                sA[2560 + base + 2 * j + 1] = pack_fp16(v[j].z - hz, v[j].w - hw);
            }
        }
    }

    // --- Epilogue: Q fp32; K/V single fp16 packed ---
#pragma unroll
    for (int mt = 0; mt < 2; ++mt) {
#pragma unroll
        for (int nt = 0; nt < 12; ++nt) {
            int n = nw * 96 + nt * 8 + (lane & 3) * 2;
            size_t r0g = (size_t)(row0 + wm + mt * 16 + (lane >> 2));
            float v0 = acc[mt][nt][0], v1 = acc[mt][nt][1];
            float v2 = acc[mt][nt][2], v3 = acc[mt][nt][3];
            if (n < 64) {
                *(float2*)&g_q[r0g * Hn + n]       = make_float2(v0, v1);
                *(float2*)&g_q[(r0g + 8) * Hn + n] = make_float2(v2, v3);
            } else {
                uint32_t* dst = (n < 128) ? g_k16 : g_v16;
                int col2 = (n & 63) >> 1;
                dst[r0g * 32 + col2]       = pack_fp16(v0, v1);
                dst[(r0g + 8) * 32 + col2] = pack_fp16(v2, v3);
            }
        }
    }
}

// ---------------------------------------------------------------------------
// Flash-attention: fp16 2-product. Q/P split hi/lo, K/V single fp16.
// 128 q-rows per block (8 warps x 16 rows), K/V staged via cp.async,
// double-buffered. Stage: [K | V], each 64 rows x 72-elem fp16 stride.
// ---------------------------------------------------------------------------
#define ARR_B   9216
#define STAGE_B (2 * ARR_B)
#define ATTN_SMEM (2 * STAGE_B)

__device__ __forceinline__ void stage_tile(uint32_t dst, int b, int kt, int tid) {
    size_t base_byte = (((size_t)b * Tn + kt * 64) * 64) * 2;
    const char* pk = (const char*)g_k16 + base_byte;
    const char* pv = (const char*)g_v16 + base_byte;
#pragma unroll
    for (int i = 0; i < 2; ++i) {
        int g = tid * 2 + i;
        uint32_t doff = (uint32_t)((g >> 3) * 144 + (g & 7) * 16);
        CP_ASYNC16(dst + 0 * ARR_B + doff, pk + g * 16);
        CP_ASYNC16(dst + 1 * ARR_B + doff, pv + g * 16);
    }
}

__global__ __launch_bounds__(256) void attn_mma_kernel(float* __restrict__ out)
{
    extern __shared__ __align__(16) char tsm[];
    const uint32_t smb = smem_u32(tsm);

    const int tid = threadIdx.x;
    const int wid = tid >> 5;
    const int lane = tid & 31;
    const int qt = blockIdx.x;        // 0..1 (128-row q tiles)
    const int b = blockIdx.y;
    const int qb = wid * 16;
    const int qbg = qt * 128 + qb;
    const int kmax = qt * 2 + 1;
    const int ri = lane & 7;
    const int tq = lane >> 3;
    const int r_lo = lane >> 2;
    const int cb = (lane & 3) * 2;

    stage_tile(smb, b, 0, tid);            CP_COMMIT();
    stage_tile(smb + STAGE_B, b, 1, tid);  CP_COMMIT();

    // --- Q fragments: fp16 hi/lo split, direct per-lane LDG ---
    uint32_t qhi[4][4], qlo[4][4];
    {
        const float* qp = g_q + ((size_t)b * Tn + qbg + r_lo) * Hn;
#pragma unroll
        for (int k16 = 0; k16 < 4; ++k16) {
            int c0 = k16 * 16 + cb;
            float2 a00 = *(const float2*)(qp + c0);
            float2 a10 = *(const float2*)(qp + 8 * Hn + c0);
            float2 a01 = *(const float2*)(qp + c0 + 8);
            float2 a11 = *(const float2*)(qp + 8 * Hn + c0 + 8);
            a00.x *= 0.125f; a00.y *= 0.125f; a10.x *= 0.125f; a10.y *= 0.125f;
            a01.x *= 0.125f; a01.y *= 0.125f; a11.x *= 0.125f; a11.y *= 0.125f;
            float h;
            h = fp16_hi_part(a00.x); float h2 = fp16_hi_part(a00.y);
            qhi[k16][0] = pack_fp16(h, h2);
            qlo[k16][0] = pack_fp16(a00.x - h, a00.y - h2);
            h = fp16_hi_part(a10.x); h2 = fp16_hi_part(a10.y);
            qhi[k16][1] = pack_fp16(h, h2);
            qlo[k16][1] = pack_fp16(a10.x - h, a10.y - h2);
            h = fp16_hi_part(a01.x); h2 = fp16_hi_part(a01.y);
            qhi[k16][2] = pack_fp16(h, h2);
            qlo[k16][2] = pack_fp16(a01.x - h, a01.y - h2);
            h = fp16_hi_part(a11.x); h2 = fp16_hi_part(a11.y);
            qhi[k16][3] = pack_fp16(h, h2);
            qlo[k16][3] = pack_fp16(a11.x - h, a11.y - h2);
        }
    }

    float o[8][4];
#pragma unroll
    for (int nt = 0; nt < 8; ++nt)
#pragma unroll
        for (int e = 0; e < 4; ++e) o[nt][e] = 0.f;
    float m0 = -1e30f, m1 = -1e30f, l0 = 0.f, l1 = 0.f;

    for (int kt = 0; kt <= kmax; ++kt) {
        CP_WAIT(1);
        __syncthreads();

        const uint32_t stb = smb + (kt & 1) * STAGE_B;
        const bool active = (kt * 64) <= (qbg + 15);

        if (active) {
            // --- S = Q K^T : 2-product fp16 ---
            float s[8][4];
#pragma unroll
            for (int nt = 0; nt < 8; ++nt)
#pragma unroll
                for (int e = 0; e < 4; ++e) s[nt][e] = 0.f;

#pragma unroll
            for (int k16 = 0; k16 < 4; ++k16) {
#pragma unroll
                for (int np = 0; np < 4; ++np) {
                    int krow = np * 16 + (tq >> 1) * 8 + ri;
                    int h = k16 * 16 + (tq & 1) * 8;
                    uint32_t kh[4];
                    ldmatrix_x4(kh, stb + 0 * ARR_B + krow * 144 + h * 2);
                    mma_fp16(s[2 * np],     qhi[k16], kh[0], kh[1]);
                    mma_fp16(s[2 * np],     qlo[k16], kh[0], kh[1]);
                    mma_fp16(s[2 * np + 1], qhi[k16], kh[2], kh[3]);
                    mma_fp16(s[2 * np + 1], qlo[k16], kh[2], kh[3]);
                }
            }

            if (kt * 64 + 63 > qbg) {
                int r0 = qbg + r_lo, r1 = r0 + 8;
#pragma unroll
                for (int nt = 0; nt < 8; ++nt) {
                    int kc = kt * 64 + nt * 8 + cb;
                    if (kc > r0)     s[nt][0] = -1e30f;
                    if (kc + 1 > r0) s[nt][1] = -1e30f;
                    if (kc > r1)     s[nt][2] = -1e30f;
                    if (kc + 1 > r1) s[nt][3] = -1e30f;
                }
            }

            float mx0 = -1e30f, mx1 = -1e30f;
#pragma unroll
            for (int nt = 0; nt < 8; ++nt) {
                mx0 = fmaxf(mx0, fmaxf(s[nt][0], s[nt][1]));
                mx1 = fmaxf(mx1, fmaxf(s[nt][2], s[nt][3]));
            }
            mx0 = fmaxf(mx0, __shfl_xor_sync(0xffffffffu, mx0, 1));
            mx0 = fmaxf(mx0, __shfl_xor_sync(0xffffffffu, mx0, 2));
            mx1 = fmaxf(mx1, __shfl_xor_sync(0xffffffffu, mx1, 1));
            mx1 = fmaxf(mx1, __shfl_xor_sync(0xffffffffu, mx1, 2));
            float mn0 = fmaxf(m0, mx0), mn1 = fmaxf(m1, mx1);
            float fac0 = __expf(m0 - mn0), fac1 = __expf(m1 - mn1);
            m0 = mn0; m1 = mn1;

            float sum0 = 0.f, sum1 = 0.f;
#pragma unroll
            for (int nt = 0; nt < 8; ++nt) {
                s[nt][0] = __expf(s[nt][0] - mn0);
                s[nt][1] = __expf(s[nt][1] - mn0);
                s[nt][2] = __expf(s[nt][2] - mn1);
                s[nt][3] = __expf(s[nt][3] - mn1);
                sum0 += s[nt][0] + s[nt][1];
                sum1 += s[nt][2] + s[nt][3];
            }
            sum0 += __shfl_xor_sync(0xffffffffu, sum0, 1);
            sum0 += __shfl_xor_sync(0xffffffffu, sum0, 2);
            sum1 += __shfl_xor_sync(0xffffffffu, sum1, 1);
            sum1 += __shfl_xor_sync(0xffffffffu, sum1, 2);
            l0 = l0 * fac0 + sum0;
            l1 = l1 * fac1 + sum1;

#pragma unroll
            for (int nt = 0; nt < 8; ++nt) {
                o[nt][0] *= fac0; o[nt][1] *= fac0;
                o[nt][2] *= fac1; o[nt][3] *= fac1;
            }

            // --- O += P V : P split fp16 hi/lo, V single fp16 ---
#pragma unroll
            for (int kv = 0; kv < 4; ++kv) {
                uint32_t pa_hi[4], pa_lo[4];
                {
                    float p00 = s[2 * kv][0],     p01 = s[2 * kv][1];
                    float p02 = s[2 * kv][2],     p03 = s[2 * kv][3];
                    float p10 = s[2 * kv + 1][0], p11 = s[2 * kv + 1][1];
                    float p12 = s[2 * kv + 1][2], p13 = s[2 * kv + 1][3];
                    float h0 = fp16_hi_part(p00), h1 = fp16_hi_part(p01);
                    float h2 = fp16_hi_part(p02), h3 = fp16_hi_part(p03);
                    float h4 = fp16_hi_part(p10), h5 = fp16_hi_part(p11);
                    float h6 = fp16_hi_part(p12), h7 = fp16_hi_part(p13);
                    pa_hi[0] = pack_fp16(h0, h1);
                    pa_hi[1] = pack_fp16(h2, h3);
                    pa_hi[2] = pack_fp16(h4, h5);
                    pa_hi[3] = pack_fp16(h6, h7);
                    pa_lo[0] = pack_fp16(p00 - h0, p01 - h1);
                    pa_lo[1] = pack_fp16(p02 - h2, p03 - h3);
                    pa_lo[2] = pack_fp16(p10 - h4, p11 - h5);
                    pa_lo[3] = pack_fp16(p12 - h6, p13 - h7);
                }
#pragma unroll
                for (int np = 0; np < 4; ++np) {
                    int krow = kv * 16 + (tq & 1) * 8 + ri;
                    int h = np * 16 + (tq >> 1) * 8;
                    uint32_t vh[4];
                    ldmatrix_x4_trans(vh, stb + 1 * ARR_B + krow * 144 + h * 2);
                    mma_fp16(o[2 * np],     pa_hi, vh[0], vh[1]);
                    mma_fp16(o[2 * np],     pa_lo, vh[0], vh[1]);
                    mma_fp16(o[2 * np + 1], pa_hi, vh[2], vh[3]);
                    mma_fp16(o[2 * np + 1], pa_lo, vh[2], vh[3]);
                }
            }
        }

        __syncthreads();
        if (kt + 2 <= kmax) {
            stage_tile(smb + (kt & 1) * STAGE_B, b, kt + 2, tid);
            CP_COMMIT();
        } else {
            CP_COMMIT();
        }
    }

    float inv0 = 1.0f / l0, inv1 = 1.0f / l1;
    size_t gr0 = ((size_t)b * Tn + qbg + r_lo) * Hn;
    size_t gr1 = gr0 + 8 * Hn;
#pragma unroll
    for (int nt = 0; nt < 8; ++nt) {
        int col = nt * 8 + cb;
        *(float2*)&out[gr0 + col] = make_float2(o[nt][0] * inv0, o[nt][1] * inv0);
        *(float2*)&out[gr1 + col] = make_float2(o[nt][2] * inv1, o[nt][3] * inv1);
    }
}

// ---------------------------------------------------------------------------
extern "C" void kernel_launch(void* const* d_in, const int* in_sizes, int n_in,
                              void* d_out, int out_size)
{
    const float* x  = (const float*)d_in[0];
    const float* Wk = (const float*)d_in[1];
    const float* Wq = (const float*)d_in[2];
    const float* Wv = (const float*)d_in[3];
    float* out = (float*)d_out;

    prep_w_kernel<<<(24 * 24 * 32 + 255) / 256, 256>>>(Wk, Wq, Wv);

    cudaFuncSetAttribute(proj_mma_kernel,
                         cudaFuncAttributeMaxDynamicSharedMemorySize, PROJ_SMEM);
    proj_mma_kernel<<<(Bn * Tn) / 128, 256, PROJ_SMEM>>>(x);

    cudaFuncSetAttribute(attn_mma_kernel,
                         cudaFuncAttributeMaxDynamicSharedMemorySize, ATTN_SMEM);
    attn_mma_kernel<<<dim3(Tn / 128, Bn), 256, ATTN_SMEM>>>(out);
}

// round 10
// speedup vs baseline: 3.5961x; 1.2011x over previous
#include <cuda_runtime.h>
#include <cuda_bf16.h>
#include <cuda_fp16.h>
#include <cstdint>

#define Bn 1024
#define Tn 256
#define Cn 384
#define Hn 64

__device__ float g_q[Bn * Tn * Hn];
// K/V as fp16, packed 2 cols per uint32: idx = row*32 + col/2
__device__ __align__(16) uint32_t g_k16[Bn * Tn * 32];
__device__ __align__(16) uint32_t g_v16[Bn * Tn * 32];

// Pre-packed fp16 B fragments for mma.sync.m16n8k16 (row.col)
__device__ __align__(16) uint2 g_bfrag[24 * 24 * 32];

// ---------------------------------------------------------------------------
__device__ __forceinline__ uint32_t smem_u32(const void* p) {
    uint32_t a;
    asm("{ .reg .u64 t; cvta.to.shared.u64 t, %1; cvt.u32.u64 %0, t; }" : "=r"(a) : "l"(p));
    return a;
}
__device__ __forceinline__ uint32_t pack_fp16(float a, float b) {
    uint32_t lo = __half_as_ushort(__float2half_rn(a));
    uint32_t hi = __half_as_ushort(__float2half_rn(b));
    return lo | (hi << 16);
}
__device__ __forceinline__ float fp16_hi_part(float v) {
    return __half2float(__float2half_rn(v));
}
__device__ __forceinline__ void mma_fp16(float* c, const uint32_t* a,
                                         uint32_t b0, uint32_t b1) {
    asm volatile(
        "mma.sync.aligned.m16n8k16.row.col.f32.f16.f16.f32 "
        "{%0,%1,%2,%3}, {%4,%5,%6,%7}, {%8,%9}, {%0,%1,%2,%3};"
        : "+f"(c[0]), "+f"(c[1]), "+f"(c[2]), "+f"(c[3])
        : "r"(a[0]), "r"(a[1]), "r"(a[2]), "r"(a[3]), "r"(b0), "r"(b1));
}
__device__ __forceinline__ void ldmatrix_x4(uint32_t* r, uint32_t addr) {
    asm volatile(
        "ldmatrix.sync.aligned.m8n8.x4.shared.b16 {%0,%1,%2,%3}, [%4];"
        : "=r"(r[0]), "=r"(r[1]), "=r"(r[2]), "=r"(r[3]) : "r"(addr));
}
__device__ __forceinline__ void ldmatrix_x4_trans(uint32_t* r, uint32_t addr) {
    asm volatile(
        "ldmatrix.sync.aligned.m8n8.x4.trans.shared.b16 {%0,%1,%2,%3}, [%4];"
        : "=r"(r[0]), "=r"(r[1]), "=r"(r[2]), "=r"(r[3]) : "r"(addr));
}
#define CP_ASYNC16(dst, src) \
    asm volatile("cp.async.cg.shared.global [%0], [%1], 16;" :: "r"(dst), "l"(src))
#define CP_COMMIT() asm volatile("cp.async.commit_group;" ::: "memory")
#define CP_WAIT(n)  asm volatile("cp.async.wait_group %0;" :: "n"(n) : "memory")

// ---------------------------------------------------------------------------
// Weight prep: fp16 W fragments in mma.sync register layout.
// ---------------------------------------------------------------------------
__global__ void prep_w_kernel(const float* __restrict__ Wk,
                              const float* __restrict__ Wq,
                              const float* __restrict__ Wv) {
    int idx = blockIdx.x * 256 + threadIdx.x;
    if (idx >= 24 * 24 * 32) return;
    int lane = idx & 31;
    int nt = (idx >> 5) % 24;
    int kt = (idx >> 5) / 24;

    int n = nt * 8 + (lane >> 2);
    int k0 = kt * 16 + (lane & 3) * 2;
    const float* W = (n < 64) ? Wq : (n < 128) ? Wk : Wv;
    int nc = n & 63;

    uint2 f;
    f.x = pack_fp16(W[(k0 + 0) * Hn + nc], W[(k0 + 1) * Hn + nc]);
    f.y = pack_fp16(W[(k0 + 8) * Hn + nc], W[(k0 + 9) * Hn + nc]);
    g_bfrag[idx] = f;
}

// ---------------------------------------------------------------------------
// Projection GEMM: single-product fp16 (x and W both fp16-rounded, f32 accum).
// Block tile M=128, N=192; 8 warps (4 x M, 2 x N). 12 k-chunks of 32.
// sA: 2 stages x 128 rows x 20 u32 (80B stride, conflict-free ldmatrix).
// ---------------------------------------------------------------------------
#define SB_OFF_U8 20480
#define PROJ_SMEM (20480 + 2 * 12288)

__global__ __launch_bounds__(256) void proj_mma_kernel(const float* __restrict__ x) {
    extern __shared__ __align__(16) char psm[];
    uint32_t* sA = (uint32_t*)psm;                 // [st*2560 + row*20 + col]
    uint2*    sB = (uint2*)(psm + SB_OFF_U8);      // [st*1536 + frag]

    const int tid = threadIdx.x;
    const int wid = tid >> 5;
    const int lane = tid & 31;
    const int row0 = blockIdx.x * 128;

    const int wm = (wid & 3) * 32;
    const int nw = wid >> 2;

    const int xr = tid >> 1;
    const int xc = (tid & 1) * 16;
    const float* xrow = x + (size_t)(row0 + xr) * Cn + xc;
    const char* gB = (const char*)g_bfrag;

#pragma unroll
    for (int j = 0; j < 3; ++j)
        CP_ASYNC16(smem_u32((char*)sB + (tid + j * 256) * 16),
                   gB + (tid + j * 256) * 16);
    CP_COMMIT();

    float4 v[4];
#pragma unroll
    for (int j = 0; j < 4; ++j) v[j] = __ldg((const float4*)xrow + j);
    {
        const int base = xr * 20 + xc / 2;
#pragma unroll
        for (int j = 0; j < 4; ++j) {
            sA[base + 2 * j + 0] = pack_fp16(v[j].x, v[j].y);
            sA[base + 2 * j + 1] = pack_fp16(v[j].z, v[j].w);
        }
    }

    float acc[2][12][4];
#pragma unroll
    for (int mt = 0; mt < 2; ++mt)
#pragma unroll
        for (int nt = 0; nt < 12; ++nt)
#pragma unroll
            for (int e = 0; e < 4; ++e) acc[mt][nt][e] = 0.f;

    const int lrow = lane & 15;
    const int lk8 = (lane >> 4) * 8;

    for (int c = 0; c < 12; ++c) {
        const int st = c & 1;

        if (c < 11) {
#pragma unroll
            for (int j = 0; j < 3; ++j)
                CP_ASYNC16(smem_u32((char*)sB + (st ^ 1) * 12288 + (tid + j * 256) * 16),
                           gB + (c + 1) * 12288 + (tid + j * 256) * 16);
            CP_COMMIT();
            const float* nx = xrow + (c + 1) * 32;
#pragma unroll
            for (int j = 0; j < 4; ++j) v[j] = __ldg((const float4*)nx + j);
        }
        if (c < 11) { CP_WAIT(1); } else { CP_WAIT(0); }
        __syncthreads();

        const uint32_t aBase = smem_u32(&sA[st * 2560]);

#pragma unroll
        for (int kt = 0; kt < 2; ++kt) {
            uint32_t af[2][4];
#pragma unroll
            for (int mt = 0; mt < 2; ++mt) {
                uint32_t off = (uint32_t)((wm + mt * 16 + lrow) * 80 +
                                          (kt * 16 + lk8) * 2);
                ldmatrix_x4(af[mt], aBase + off);
            }
            const uint2* bp = sB + (st * 1536 + ((kt * 24 + nw * 12) * 32 + lane));
#pragma unroll
            for (int nt = 0; nt < 12; ++nt) {
                uint2 bf = bp[nt * 32];
#pragma unroll
                for (int mt = 0; mt < 2; ++mt)
                    mma_fp16(acc[mt][nt], af[mt], bf.x, bf.y);
            }
        }

        if (c < 11) {
            __syncthreads();
            const int base = (st ^ 1) * 2560 + xr * 20 + xc / 2;
#pragma unroll
            for (int j = 0; j < 4; ++j) {
                sA[base + 2 * j + 0] = pack_fp16(v[j].x, v[j].y);
                sA[base + 2 * j + 1] = pack_fp16(v[j].z, v[j].w);
            }
        }
    }

    // --- Epilogue: Q fp32; K/V single fp16 packed ---
#pragma unroll
    for (int mt = 0; mt < 2; ++mt) {
#pragma unroll
        for (int nt = 0; nt < 12; ++nt) {
            int n = nw * 96 + nt * 8 + (lane & 3) * 2;
            size_t r0g = (size_t)(row0 + wm + mt * 16 + (lane >> 2));
            float v0 = acc[mt][nt][0], v1 = acc[mt][nt][1];
            float v2 = acc[mt][nt][2], v3 = acc[mt][nt][3];
            if (n < 64) {
                *(float2*)&g_q[r0g * Hn + n]       = make_float2(v0, v1);
                *(float2*)&g_q[(r0g + 8) * Hn + n] = make_float2(v2, v3);
            } else {
                uint32_t* dst = (n < 128) ? g_k16 : g_v16;
                int col2 = (n & 63) >> 1;
                dst[r0g * 32 + col2]       = pack_fp16(v0, v1);
                dst[(r0g + 8) * 32 + col2] = pack_fp16(v2, v3);
            }
        }
    }
}

// ---------------------------------------------------------------------------
// Flash-attention: unchanged from R9 (fp16 2-product, passing @ 4.16e-4).
// ---------------------------------------------------------------------------
#define ARR_B   9216
#define STAGE_B (2 * ARR_B)
#define ATTN_SMEM (2 * STAGE_B)

__device__ __forceinline__ void stage_tile(uint32_t dst, int b, int kt, int tid) {
    size_t base_byte = (((size_t)b * Tn + kt * 64) * 64) * 2;
    const char* pk = (const char*)g_k16 + base_byte;
    const char* pv = (const char*)g_v16 + base_byte;
#pragma unroll
    for (int i = 0; i < 2; ++i) {
        int g = tid * 2 + i;
        uint32_t doff = (uint32_t)((g >> 3) * 144 + (g & 7) * 16);
        CP_ASYNC16(dst + 0 * ARR_B + doff, pk + g * 16);
        CP_ASYNC16(dst + 1 * ARR_B + doff, pv + g * 16);
    }
}

__global__ __launch_bounds__(256) void attn_mma_kernel(float* __restrict__ out)
{
    extern __shared__ __align__(16) char tsm[];
    const uint32_t smb = smem_u32(tsm);

    const int tid = threadIdx.x;
    const int wid = tid >> 5;
    const int lane = tid & 31;
    const int qt = blockIdx.x;
    const int b = blockIdx.y;
    const int qb = wid * 16;
    const int qbg = qt * 128 + qb;
    const int kmax = qt * 2 + 1;
    const int ri = lane & 7;
    const int tq = lane >> 3;
    const int r_lo = lane >> 2;
    const int cb = (lane & 3) * 2;

    stage_tile(smb, b, 0, tid);            CP_COMMIT();
    stage_tile(smb + STAGE_B, b, 1, tid);  CP_COMMIT();

    uint32_t qhi[4][4], qlo[4][4];
    {
        const float* qp = g_q + ((size_t)b * Tn + qbg + r_lo) * Hn;
#pragma unroll
        for (int k16 = 0; k16 < 4; ++k16) {
            int c0 = k16 * 16 + cb;
            float2 a00 = *(const float2*)(qp + c0);
            float2 a10 = *(const float2*)(qp + 8 * Hn + c0);
            float2 a01 = *(const float2*)(qp + c0 + 8);
            float2 a11 = *(const float2*)(qp + 8 * Hn + c0 + 8);
            a00.x *= 0.125f; a00.y *= 0.125f; a10.x *= 0.125f; a10.y *= 0.125f;
            a01.x *= 0.125f; a01.y *= 0.125f; a11.x *= 0.125f; a11.y *= 0.125f;
            float h, h2;
            h = fp16_hi_part(a00.x); h2 = fp16_hi_part(a00.y);
            qhi[k16][0] = pack_fp16(h, h2);
            qlo[k16][0] = pack_fp16(a00.x - h, a00.y - h2);
            h = fp16_hi_part(a10.x); h2 = fp16_hi_part(a10.y);
            qhi[k16][1] = pack_fp16(h, h2);
            qlo[k16][1] = pack_fp16(a10.x - h, a10.y - h2);
            h = fp16_hi_part(a01.x); h2 = fp16_hi_part(a01.y);
            qhi[k16][2] = pack_fp16(h, h2);
            qlo[k16][2] = pack_fp16(a01.x - h, a01.y - h2);
            h = fp16_hi_part(a11.x); h2 = fp16_hi_part(a11.y);
            qhi[k16][3] = pack_fp16(h, h2);
            qlo[k16][3] = pack_fp16(a11.x - h, a11.y - h2);
        }
    }

    float o[8][4];
#pragma unroll
    for (int nt = 0; nt < 8; ++nt)
#pragma unroll
        for (int e = 0; e < 4; ++e) o[nt][e] = 0.f;
    float m0 = -1e30f, m1 = -1e30f, l0 = 0.f, l1 = 0.f;

    for (int kt = 0; kt <= kmax; ++kt) {
        CP_WAIT(1);
        __syncthreads();

        const uint32_t stb = smb + (kt & 1) * STAGE_B;
        const bool active = (kt * 64) <= (qbg + 15);

        if (active) {
            float s[8][4];
#pragma unroll
            for (int nt = 0; nt < 8; ++nt)
#pragma unroll
                for (int e = 0; e < 4; ++e) s[nt][e] = 0.f;

#pragma unroll
            for (int k16 = 0; k16 < 4; ++k16) {
#pragma unroll
                for (int np = 0; np < 4; ++np) {
                    int krow = np * 16 + (tq >> 1) * 8 + ri;
                    int h = k16 * 16 + (tq & 1) * 8;
                    uint32_t kh[4];
                    ldmatrix_x4(kh, stb + 0 * ARR_B + krow * 144 + h * 2);
                    mma_fp16(s[2 * np],     qhi[k16], kh[0], kh[1]);
                    mma_fp16(s[2 * np],     qlo[k16], kh[0], kh[1]);
                    mma_fp16(s[2 * np + 1], qhi[k16], kh[2], kh[3]);
                    mma_fp16(s[2 * np + 1], qlo[k16], kh[2], kh[3]);
                }
            }

            if (kt * 64 + 63 > qbg) {
                int r0 = qbg + r_lo, r1 = r0 + 8;
#pragma unroll
                for (int nt = 0; nt < 8; ++nt) {
                    int kc = kt * 64 + nt * 8 + cb;
                    if (kc > r0)     s[nt][0] = -1e30f;
                    if (kc + 1 > r0) s[nt][1] = -1e30f;
                    if (kc > r1)     s[nt][2] = -1e30f;
                    if (kc + 1 > r1) s[nt][3] = -1e30f;
                }
            }

            float mx0 = -1e30f, mx1 = -1e30f;
#pragma unroll
            for (int nt = 0; nt < 8; ++nt) {
                mx0 = fmaxf(mx0, fmaxf(s[nt][0], s[nt][1]));
                mx1 = fmaxf(mx1, fmaxf(s[nt][2], s[nt][3]));
            }
            mx0 = fmaxf(mx0, __shfl_xor_sync(0xffffffffu, mx0, 1));
            mx0 = fmaxf(mx0, __shfl_xor_sync(0xffffffffu, mx0, 2));
            mx1 = fmaxf(mx1, __shfl_xor_sync(0xffffffffu, mx1, 1));
            mx1 = fmaxf(mx1, __shfl_xor_sync(0xffffffffu, mx1, 2));
            float mn0 = fmaxf(m0, mx0), mn1 = fmaxf(m1, mx1);
            float fac0 = __expf(m0 - mn0), fac1 = __expf(m1 - mn1);
            m0 = mn0; m1 = mn1;

            float sum0 = 0.f, sum1 = 0.f;
#pragma unroll
            for (int nt = 0; nt < 8; ++nt) {
                s[nt][0] = __expf(s[nt][0] - mn0);
                s[nt][1] = __expf(s[nt][1] - mn0);
                s[nt][2] = __expf(s[nt][2] - mn1);
                s[nt][3] = __expf(s[nt][3] - mn1);
                sum0 += s[nt][0] + s[nt][1];
                sum1 += s[nt][2] + s[nt][3];
            }
            sum0 += __shfl_xor_sync(0xffffffffu, sum0, 1);
            sum0 += __shfl_xor_sync(0xffffffffu, sum0, 2);
            sum1 += __shfl_xor_sync(0xffffffffu, sum1, 1);
            sum1 += __shfl_xor_sync(0xffffffffu, sum1, 2);
            l0 = l0 * fac0 + sum0;
            l1 = l1 * fac1 + sum1;

#pragma unroll
            for (int nt = 0; nt < 8; ++nt) {
                o[nt][0] *= fac0; o[nt][1] *= fac0;
                o[nt][2] *= fac1; o[nt][3] *= fac1;
            }

#pragma unroll
            for (int kv = 0; kv < 4; ++kv) {
                uint32_t pa_hi[4], pa_lo[4];
                {
                    float p00 = s[2 * kv][0],     p01 = s[2 * kv][1];
                    float p02 = s[2 * kv][2],     p03 = s[2 * kv][3];
                    float p10 = s[2 * kv + 1][0], p11 = s[2 * kv + 1][1];
                    float p12 = s[2 * kv + 1][2], p13 = s[2 * kv + 1][3];
                    float h0 = fp16_hi_part(p00), h1 = fp16_hi_part(p01);
                    float h2 = fp16_hi_part(p02), h3 = fp16_hi_part(p03);
                    float h4 = fp16_hi_part(p10), h5 = fp16_hi_part(p11);
                    float h6 = fp16_hi_part(p12), h7 = fp16_hi_part(p13);
                    pa_hi[0] = pack_fp16(h0, h1);
                    pa_hi[1] = pack_fp16(h2, h3);
                    pa_hi[2] = pack_fp16(h4, h5);
                    pa_hi[3] = pack_fp16(h6, h7);
                    pa_lo[0] = pack_fp16(p00 - h0, p01 - h1);
                    pa_lo[1] = pack_fp16(p02 - h2, p03 - h3);
                    pa_lo[2] = pack_fp16(p10 - h4, p11 - h5);
                    pa_lo[3] = pack_fp16(p12 - h6, p13 - h7);
                }
#pragma unroll
                for (int np = 0; np < 4; ++np) {
                    int krow = kv * 16 + (tq & 1) * 8 + ri;
                    int h = np * 16 + (tq >> 1) * 8;
                    uint32_t vh[4];
                    ldmatrix_x4_trans(vh, stb + 1 * ARR_B + krow * 144 + h * 2);
                    mma_fp16(o[2 * np],     pa_hi, vh[0], vh[1]);
                    mma_fp16(o[2 * np],     pa_lo, vh[0], vh[1]);
                    mma_fp16(o[2 * np + 1], pa_hi, vh[2], vh[3]);
                    mma_fp16(o[2 * np + 1], pa_lo, vh[2], vh[3]);
                }
            }
        }

        __syncthreads();
        if (kt + 2 <= kmax) {
            stage_tile(smb + (kt & 1) * STAGE_B, b, kt + 2, tid);
            CP_COMMIT();
        } else {
            CP_COMMIT();
        }
    }

    float inv0 = 1.0f / l0, inv1 = 1.0f / l1;
    size_t gr0 = ((size_t)b * Tn + qbg + r_lo) * Hn;
    size_t gr1 = gr0 + 8 * Hn;
#pragma unroll
    for (int nt = 0; nt < 8; ++nt) {
        int col = nt * 8 + cb;
        *(float2*)&out[gr0 + col] = make_float2(o[nt][0] * inv0, o[nt][1] * inv0);
        *(float2*)&out[gr1 + col] = make_float2(o[nt][2] * inv1, o[nt][3] * inv1);
    }
}

// ---------------------------------------------------------------------------
extern "C" void kernel_launch(void* const* d_in, const int* in_sizes, int n_in,
                              void* d_out, int out_size)
{
    const float* x  = (const float*)d_in[0];
    const float* Wk = (const float*)d_in[1];
    const float* Wq = (const float*)d_in[2];
    const float* Wv = (const float*)d_in[3];
    float* out = (float*)d_out;

    prep_w_kernel<<<(24 * 24 * 32 + 255) / 256, 256>>>(Wk, Wq, Wv);

    cudaFuncSetAttribute(proj_mma_kernel,
                         cudaFuncAttributeMaxDynamicSharedMemorySize, PROJ_SMEM);
    proj_mma_kernel<<<(Bn * Tn) / 128, 256, PROJ_SMEM>>>(x);

    cudaFuncSetAttribute(attn_mma_kernel,
                         cudaFuncAttributeMaxDynamicSharedMemorySize, ATTN_SMEM);
    attn_mma_kernel<<<dim3(Tn / 128, Bn), 256, ATTN_SMEM>>>(out);
}

// round 11
// speedup vs baseline: 4.4271x; 1.2311x over previous
#include <cuda_runtime.h>
#include <cuda_bf16.h>
#include <cuda_fp16.h>
#include <cstdint>

#define Bn 1024
#define Tn 256
#define Cn 384
#define Hn 64

// Q/K/V as fp16, packed 2 cols per uint32: idx = row*32 + col/2.
// Q is pre-scaled by 0.125 (exact, power of two).
__device__ __align__(16) uint32_t g_q16[Bn * Tn * 32];
__device__ __align__(16) uint32_t g_k16[Bn * Tn * 32];
__device__ __align__(16) uint32_t g_v16[Bn * Tn * 32];

// Pre-packed fp16 B fragments for mma.sync.m16n8k16 (row.col)
__device__ __align__(16) uint2 g_bfrag[24 * 24 * 32];

// ---------------------------------------------------------------------------
__device__ __forceinline__ uint32_t smem_u32(const void* p) {
    uint32_t a;
    asm("{ .reg .u64 t; cvta.to.shared.u64 t, %1; cvt.u32.u64 %0, t; }" : "=r"(a) : "l"(p));
    return a;
}
__device__ __forceinline__ uint32_t pack_fp16(float a, float b) {
    uint32_t lo = __half_as_ushort(__float2half_rn(a));
    uint32_t hi = __half_as_ushort(__float2half_rn(b));
    return lo | (hi << 16);
}
__device__ __forceinline__ void mma_fp16(float* c, const uint32_t* a,
                                         uint32_t b0, uint32_t b1) {
    asm volatile(
        "mma.sync.aligned.m16n8k16.row.col.f32.f16.f16.f32 "
        "{%0,%1,%2,%3}, {%4,%5,%6,%7}, {%8,%9}, {%0,%1,%2,%3};"
        : "+f"(c[0]), "+f"(c[1]), "+f"(c[2]), "+f"(c[3])
        : "r"(a[0]), "r"(a[1]), "r"(a[2]), "r"(a[3]), "r"(b0), "r"(b1));
}
__device__ __forceinline__ void ldmatrix_x4(uint32_t* r, uint32_t addr) {
    asm volatile(
        "ldmatrix.sync.aligned.m8n8.x4.shared.b16 {%0,%1,%2,%3}, [%4];"
        : "=r"(r[0]), "=r"(r[1]), "=r"(r[2]), "=r"(r[3]) : "r"(addr));
}
__device__ __forceinline__ void ldmatrix_x4_trans(uint32_t* r, uint32_t addr) {
    asm volatile(
        "ldmatrix.sync.aligned.m8n8.x4.trans.shared.b16 {%0,%1,%2,%3}, [%4];"
        : "=r"(r[0]), "=r"(r[1]), "=r"(r[2]), "=r"(r[3]) : "r"(addr));
}
#define CP_ASYNC16(dst, src) \
    asm volatile("cp.async.cg.shared.global [%0], [%1], 16;" :: "r"(dst), "l"(src))
#define CP_COMMIT() asm volatile("cp.async.commit_group;" ::: "memory")
#define CP_WAIT(n)  asm volatile("cp.async.wait_group %0;" :: "n"(n) : "memory")

// ---------------------------------------------------------------------------
// Weight prep: fp16 W fragments in mma.sync register layout.
// ---------------------------------------------------------------------------
__global__ void prep_w_kernel(const float* __restrict__ Wk,
                              const float* __restrict__ Wq,
                              const float* __restrict__ Wv) {
    int idx = blockIdx.x * 256 + threadIdx.x;
    if (idx >= 24 * 24 * 32) return;
    int lane = idx & 31;
    int nt = (idx >> 5) % 24;
    int kt = (idx >> 5) / 24;

    int n = nt * 8 + (lane >> 2);
    int k0 = kt * 16 + (lane & 3) * 2;
    const float* W = (n < 64) ? Wq : (n < 128) ? Wk : Wv;
    int nc = n & 63;

    uint2 f;
    f.x = pack_fp16(W[(k0 + 0) * Hn + nc], W[(k0 + 1) * Hn + nc]);
    f.y = pack_fp16(W[(k0 + 8) * Hn + nc], W[(k0 + 9) * Hn + nc]);
    g_bfrag[idx] = f;
}

// ---------------------------------------------------------------------------
// Projection GEMM: single-product fp16, one sync per k-chunk.
// Block tile M=128, N=192; 8 warps (4 x M, 2 x N). 12 k-chunks of 32.
// ---------------------------------------------------------------------------
#define SB_OFF_U8 20480
#define PROJ_SMEM (20480 + 2 * 12288)

__global__ __launch_bounds__(256) void proj_mma_kernel(const float* __restrict__ x) {
    extern __shared__ __align__(16) char psm[];
    uint32_t* sA = (uint32_t*)psm;                 // [st*2560 + row*20 + col]
    uint2*    sB = (uint2*)(psm + SB_OFF_U8);      // [st*1536 + frag]

    const int tid = threadIdx.x;
    const int wid = tid >> 5;
    const int lane = tid & 31;
    const int row0 = blockIdx.x * 128;

    const int wm = (wid & 3) * 32;
    const int nw = wid >> 2;

    const int xr = tid >> 1;
    const int xc = (tid & 1) * 16;
    const float* xrow = x + (size_t)(row0 + xr) * Cn + xc;
    const char* gB = (const char*)g_bfrag;

#pragma unroll
    for (int j = 0; j < 3; ++j)
        CP_ASYNC16(smem_u32((char*)sB + (tid + j * 256) * 16),
                   gB + (tid + j * 256) * 16);
    CP_COMMIT();

    float4 v[4];
#pragma unroll
    for (int j = 0; j < 4; ++j) v[j] = __ldg((const float4*)xrow + j);
    {
        const int base = xr * 20 + xc / 2;
#pragma unroll
        for (int j = 0; j < 4; ++j) {
            sA[base + 2 * j + 0] = pack_fp16(v[j].x, v[j].y);
            sA[base + 2 * j + 1] = pack_fp16(v[j].z, v[j].w);
        }
    }

    float acc[2][12][4];
#pragma unroll
    for (int mt = 0; mt < 2; ++mt)
#pragma unroll
        for (int nt = 0; nt < 12; ++nt)
#pragma unroll
            for (int e = 0; e < 4; ++e) acc[mt][nt][e] = 0.f;

    const int lrow = lane & 15;
    const int lk8 = (lane >> 4) * 8;

    for (int c = 0; c < 12; ++c) {
        const int st = c & 1;

        if (c < 11) {
#pragma unroll
            for (int j = 0; j < 3; ++j)
                CP_ASYNC16(smem_u32((char*)sB + (st ^ 1) * 12288 + (tid + j * 256) * 16),
                           gB + (c + 1) * 12288 + (tid + j * 256) * 16);
            CP_COMMIT();
            const float* nx = xrow + (c + 1) * 32;
#pragma unroll
            for (int j = 0; j < 4; ++j) v[j] = __ldg((const float4*)nx + j);
        }
        if (c < 11) { CP_WAIT(1); } else { CP_WAIT(0); }
        __syncthreads();   // B_c arrived + A_c visible; prior readers of st done

        const uint32_t aBase = smem_u32(&sA[st * 2560]);

#pragma unroll
        for (int kt = 0; kt < 2; ++kt) {
            uint32_t af[2][4];
#pragma unroll
            for (int mt = 0; mt < 2; ++mt) {
                uint32_t off = (uint32_t)((wm + mt * 16 + lrow) * 80 +
                                          (kt * 16 + lk8) * 2);
                ldmatrix_x4(af[mt], aBase + off);
            }
            const uint2* bp = sB + (st * 1536 + ((kt * 24 + nw * 12) * 32 + lane));
#pragma unroll
            for (int nt = 0; nt < 12; ++nt) {
                uint2 bf = bp[nt * 32];
#pragma unroll
                for (int mt = 0; mt < 2; ++mt)
                    mma_fp16(acc[mt][nt], af[mt], bf.x, bf.y);
            }
        }

        // Restage A for chunk c+1 into the other stage. No barrier needed:
        // chunk c-1's readers of sA[st^1] completed before this chunk's sync,
        // and chunk c+1's readers are guarded by its own sync.
        if (c < 11) {
            const int base = (st ^ 1) * 2560 + xr * 20 + xc / 2;
#pragma unroll
            for (int j = 0; j < 4; ++j) {
                sA[base + 2 * j + 0] = pack_fp16(v[j].x, v[j].y);
                sA[base + 2 * j + 1] = pack_fp16(v[j].z, v[j].w);
            }
        }
    }

    // --- Epilogue: Q (pre-scaled), K, V all fp16 packed ---
#pragma unroll
    for (int mt = 0; mt < 2; ++mt) {
#pragma unroll
        for (int nt = 0; nt < 12; ++nt) {
            int n = nw * 96 + nt * 8 + (lane & 3) * 2;
            size_t r0g = (size_t)(row0 + wm + mt * 16 + (lane >> 2));
            float v0 = acc[mt][nt][0], v1 = acc[mt][nt][1];
            float v2 = acc[mt][nt][2], v3 = acc[mt][nt][3];
            uint32_t* dst;
            float sc;
            if (n < 64)      { dst = g_q16; sc = 0.125f; }
            else if (n < 128){ dst = g_k16; sc = 1.0f; }
            else             { dst = g_v16; sc = 1.0f; }
            int col2 = (n & 63) >> 1;
            dst[r0g * 32 + col2]       = pack_fp16(v0 * sc, v1 * sc);
            dst[(r0g + 8) * 32 + col2] = pack_fp16(v2 * sc, v3 * sc);
        }
    }
}

// ---------------------------------------------------------------------------
// Flash-attention: single-product fp16 throughout. Q pre-rounded fp16 from
// proj; P rounded to fp16. 128 q-rows per block (8 warps x 16 rows), K/V
// staged via cp.async, double-buffered.
// ---------------------------------------------------------------------------
#define ARR_B   9216
#define STAGE_B (2 * ARR_B)
#define ATTN_SMEM (2 * STAGE_B)

__device__ __forceinline__ void stage_tile(uint32_t dst, int b, int kt, int tid) {
    size_t base_byte = (((size_t)b * Tn + kt * 64) * 64) * 2;
    const char* pk = (const char*)g_k16 + base_byte;
    const char* pv = (const char*)g_v16 + base_byte;
#pragma unroll
    for (int i = 0; i < 2; ++i) {
        int g = tid * 2 + i;
        uint32_t doff = (uint32_t)((g >> 3) * 144 + (g & 7) * 16);
        CP_ASYNC16(dst + 0 * ARR_B + doff, pk + g * 16);
        CP_ASYNC16(dst + 1 * ARR_B + doff, pv + g * 16);
    }
}

__global__ __launch_bounds__(256) void attn_mma_kernel(float* __restrict__ out)
{
    extern __shared__ __align__(16) char tsm[];
    const uint32_t smb = smem_u32(tsm);

    const int tid = threadIdx.x;
    const int wid = tid >> 5;
    const int lane = tid & 31;
    const int qt = blockIdx.x;
    const int b = blockIdx.y;
    const int qb = wid * 16;
    const int qbg = qt * 128 + qb;
    const int kmax = qt * 2 + 1;
    const int ri = lane & 7;
    const int tq = lane >> 3;
    const int r_lo = lane >> 2;
    const int cb = (lane & 3) * 2;

    stage_tile(smb, b, 0, tid);            CP_COMMIT();
    stage_tile(smb + STAGE_B, b, 1, tid);  CP_COMMIT();

    // --- Q A-fragments: direct LDG of pre-scaled, pre-rounded fp16 pairs ---
    uint32_t qf[4][4];
    {
        const uint32_t* qp = g_q16 + ((size_t)b * Tn + qbg + r_lo) * 32;
#pragma unroll
        for (int k16 = 0; k16 < 4; ++k16) {
            int c2 = (k16 * 16 + cb) >> 1;
            qf[k16][0] = __ldg(qp + c2);
            qf[k16][1] = __ldg(qp + 8 * 32 + c2);
            qf[k16][2] = __ldg(qp + c2 + 4);
            qf[k16][3] = __ldg(qp + 8 * 32 + c2 + 4);
        }
    }

    float o[8][4];
#pragma unroll
    for (int nt = 0; nt < 8; ++nt)
#pragma unroll
        for (int e = 0; e < 4; ++e) o[nt][e] = 0.f;
    float m0 = -1e30f, m1 = -1e30f, l0 = 0.f, l1 = 0.f;

    for (int kt = 0; kt <= kmax; ++kt) {
        CP_WAIT(1);
        __syncthreads();

        const uint32_t stb = smb + (kt & 1) * STAGE_B;
        const bool active = (kt * 64) <= (qbg + 15);

        if (active) {
            // --- S = Q K^T : single-product fp16 ---
            float s[8][4];
#pragma unroll
            for (int nt = 0; nt < 8; ++nt)
#pragma unroll
                for (int e = 0; e < 4; ++e) s[nt][e] = 0.f;

#pragma unroll
            for (int k16 = 0; k16 < 4; ++k16) {
#pragma unroll
                for (int np = 0; np < 4; ++np) {
                    int krow = np * 16 + (tq >> 1) * 8 + ri;
                    int h = k16 * 16 + (tq & 1) * 8;
                    uint32_t kh[4];
                    ldmatrix_x4(kh, stb + 0 * ARR_B + krow * 144 + h * 2);
                    mma_fp16(s[2 * np],     qf[k16], kh[0], kh[1]);
                    mma_fp16(s[2 * np + 1], qf[k16], kh[2], kh[3]);
                }
            }

            if (kt * 64 + 63 > qbg) {
                int r0 = qbg + r_lo, r1 = r0 + 8;
#pragma unroll
                for (int nt = 0; nt < 8; ++nt) {
                    int kc = kt * 64 + nt * 8 + cb;
                    if (kc > r0)     s[nt][0] = -1e30f;
                    if (kc + 1 > r0) s[nt][1] = -1e30f;
                    if (kc > r1)     s[nt][2] = -1e30f;
                    if (kc + 1 > r1) s[nt][3] = -1e30f;
                }
            }

            float mx0 = -1e30f, mx1 = -1e30f;
#pragma unroll
            for (int nt = 0; nt < 8; ++nt) {
                mx0 = fmaxf(mx0, fmaxf(s[nt][0], s[nt][1]));
                mx1 = fmaxf(mx1, fmaxf(s[nt][2], s[nt][3]));
            }
            mx0 = fmaxf(mx0, __shfl_xor_sync(0xffffffffu, mx0, 1));
            mx0 = fmaxf(mx0, __shfl_xor_sync(0xffffffffu, mx0, 2));
            mx1 = fmaxf(mx1, __shfl_xor_sync(0xffffffffu, mx1, 1));
            mx1 = fmaxf(mx1, __shfl_xor_sync(0xffffffffu, mx1, 2));
            float mn0 = fmaxf(m0, mx0), mn1 = fmaxf(m1, mx1);
            float fac0 = __expf(m0 - mn0), fac1 = __expf(m1 - mn1);
            m0 = mn0; m1 = mn1;

            float sum0 = 0.f, sum1 = 0.f;
#pragma unroll
            for (int nt = 0; nt < 8; ++nt) {
                s[nt][0] = __expf(s[nt][0] - mn0);
                s[nt][1] = __expf(s[nt][1] - mn0);
                s[nt][2] = __expf(s[nt][2] - mn1);
                s[nt][3] = __expf(s[nt][3] - mn1);
                sum0 += s[nt][0] + s[nt][1];
                sum1 += s[nt][2] + s[nt][3];
            }
            sum0 += __shfl_xor_sync(0xffffffffu, sum0, 1);
            sum0 += __shfl_xor_sync(0xffffffffu, sum0, 2);
            sum1 += __shfl_xor_sync(0xffffffffu, sum1, 1);
            sum1 += __shfl_xor_sync(0xffffffffu, sum1, 2);
            l0 = l0 * fac0 + sum0;
            l1 = l1 * fac1 + sum1;

#pragma unroll
            for (int nt = 0; nt < 8; ++nt) {
                o[nt][0] *= fac0; o[nt][1] *= fac0;
                o[nt][2] *= fac1; o[nt][3] *= fac1;
            }

            // --- O += P V : P single fp16 ---
#pragma unroll
            for (int kv = 0; kv < 4; ++kv) {
                uint32_t pa[4];
                pa[0] = pack_fp16(s[2 * kv][0],     s[2 * kv][1]);
                pa[1] = pack_fp16(s[2 * kv][2],     s[2 * kv][3]);
                pa[2] = pack_fp16(s[2 * kv + 1][0], s[2 * kv + 1][1]);
                pa[3] = pack_fp16(s[2 * kv + 1][2], s[2 * kv + 1][3]);
#pragma unroll
                for (int np = 0; np < 4; ++np) {
                    int krow = kv * 16 + (tq & 1) * 8 + ri;
                    int h = np * 16 + (tq >> 1) * 8;
                    uint32_t vh[4];
                    ldmatrix_x4_trans(vh, stb + 1 * ARR_B + krow * 144 + h * 2);
                    mma_fp16(o[2 * np],     pa, vh[0], vh[1]);
                    mma_fp16(o[2 * np + 1], pa, vh[2], vh[3]);
                }
            }
        }

        __syncthreads();
        if (kt + 2 <= kmax) {
            stage_tile(smb + (kt & 1) * STAGE_B, b, kt + 2, tid);
            CP_COMMIT();
        } else {
            CP_COMMIT();
        }
    }

    float inv0 = 1.0f / l0, inv1 = 1.0f / l1;
    size_t gr0 = ((size_t)b * Tn + qbg + r_lo) * Hn;
    size_t gr1 = gr0 + 8 * Hn;
#pragma unroll
    for (int nt = 0; nt < 8; ++nt) {
        int col = nt * 8 + cb;
        *(float2*)&out[gr0 + col] = make_float2(o[nt][0] * inv0, o[nt][1] * inv0);
        *(float2*)&out[gr1 + col] = make_float2(o[nt][2] * inv1, o[nt][3] * inv1);
    }
}

// ---------------------------------------------------------------------------
extern "C" void kernel_launch(void* const* d_in, const int* in_sizes, int n_in,
                              void* d_out, int out_size)
{
    const float* x  = (const float*)d_in[0];
    const float* Wk = (const float*)d_in[1];
    const float* Wq = (const float*)d_in[2];
    const float* Wv = (const float*)d_in[3];
    float* out = (float*)d_out;

    prep_w_kernel<<<(24 * 24 * 32 + 255) / 256, 256>>>(Wk, Wq, Wv);

    cudaFuncSetAttribute(proj_mma_kernel,
                         cudaFuncAttributeMaxDynamicSharedMemorySize, PROJ_SMEM);
    proj_mma_kernel<<<(Bn * Tn) / 128, 256, PROJ_SMEM>>>(x);

    cudaFuncSetAttribute(attn_mma_kernel,
                         cudaFuncAttributeMaxDynamicSharedMemorySize, ATTN_SMEM);
    attn_mma_kernel<<<dim3(Tn / 128, Bn), 256, ATTN_SMEM>>>(out);
}